// round 1
// baseline (speedup 1.0000x reference)
#include <cuda_runtime.h>
#include <cstdint>
#include <cstddef>

// Problem dims (fixed)
//  B=32, T=256, D=768, H=512, 4H=2048, N=25
// Inputs (metadata order):
//  0 embeddings [32,256,768] f32
//  1 targets    [32,256]     i32
//  2 seq_lens   [32]         i32
//  3 k_fwd [768,2048]  4 r_fwd [512,2048]  5 b_fwd [2048]
//  6 k_bwd [768,2048]  7 r_bwd [512,2048]  8 b_bwd [2048]
//  9 dense_w [1024,25] 10 dense_b [25]     11 transitions [25,25]
// Output: d_out[0] = loss, d_out[1..204800] = logits [32,256,25]

// ---------------- scratch ----------------
__device__ __align__(16) float g_xz[2ull * 8192ull * 2048ull];   // 128 MB: xz per direction
__device__ __align__(16) float g_hs[8192ull * 1024ull];          // 32 MB: [row][fwd 512 | bwd 512]
__device__ __align__(16) float g_h[2 * 2 * 32 * 512];            // [dir][buf][b][u] double-buffered h
__device__ float g_nll[32];
__device__ unsigned g_bar_count = 0;
__device__ volatile unsigned g_bar_gen = 0;

// ---------------- grid barrier (all CTAs co-resident by construction) ----------------
__device__ __forceinline__ void grid_barrier(unsigned nblocks) {
    __threadfence();
    __syncthreads();
    if (threadIdx.x == 0) {
        unsigned gen = g_bar_gen;
        __threadfence();
        unsigned t = atomicAdd(&g_bar_count, 1u);
        if (t == nblocks - 1u) {
            atomicExch(&g_bar_count, 0u);
            __threadfence();
            g_bar_gen = gen + 1u;
        } else {
            while (g_bar_gen == gen) { __nanosleep(64); }
        }
        __threadfence();
    }
    __syncthreads();
}

// ================= K1: xz = x @ K + b  (both directions) =================
// M=8192, K=768, N=2048 per dir. Tile 128x128x16, 256 threads, 8x8 per thread.
__global__ __launch_bounds__(256) void xz_gemm_kernel(
    const float* __restrict__ x,
    const float* __restrict__ kf, const float* __restrict__ bf,
    const float* __restrict__ kb, const float* __restrict__ bb)
{
    __shared__ float As[16][128];   // [k][m]
    __shared__ float Bs[16][128];   // [k][n]
    const int m0   = blockIdx.y * 128;
    const int nblk = blockIdx.x;          // 0..31
    const int dir  = nblk >> 4;
    const int n0   = (nblk & 15) * 128;   // col within this direction
    const float* __restrict__ w    = dir ? kb : kf;
    const float* __restrict__ bias = dir ? bb : bf;

    const int tid = threadIdx.x;
    const int tx = tid & 15, ty = tid >> 4;
    const int arow = tid >> 2, acol4 = tid & 3;
    const int brow = tid >> 5, bcol4 = tid & 31;

    float acc[8][8];
#pragma unroll
    for (int i = 0; i < 8; i++)
#pragma unroll
        for (int j = 0; j < 8; j++) acc[i][j] = 0.f;

    for (int k0 = 0; k0 < 768; k0 += 16) {
#pragma unroll
        for (int p = 0; p < 2; p++) {
            int r = arow + p * 64;
            float4 v = *(const float4*)&x[(size_t)(m0 + r) * 768 + k0 + acol4 * 4];
            As[acol4 * 4 + 0][r] = v.x;
            As[acol4 * 4 + 1][r] = v.y;
            As[acol4 * 4 + 2][r] = v.z;
            As[acol4 * 4 + 3][r] = v.w;
        }
#pragma unroll
        for (int p = 0; p < 2; p++) {
            int r = brow + p * 8;
            *(float4*)&Bs[r][bcol4 * 4] =
                *(const float4*)&w[(size_t)(k0 + r) * 2048 + n0 + bcol4 * 4];
        }
        __syncthreads();
#pragma unroll
        for (int k = 0; k < 16; k++) {
            float a[8], bv[8];
            *(float4*)&a[0]  = *(const float4*)&As[k][ty * 8];
            *(float4*)&a[4]  = *(const float4*)&As[k][ty * 8 + 4];
            *(float4*)&bv[0] = *(const float4*)&Bs[k][tx * 8];
            *(float4*)&bv[4] = *(const float4*)&Bs[k][tx * 8 + 4];
#pragma unroll
            for (int i = 0; i < 8; i++)
#pragma unroll
                for (int j = 0; j < 8; j++)
                    acc[i][j] = fmaf(a[i], bv[j], acc[i][j]);
        }
        __syncthreads();
    }

    float* out = g_xz + (size_t)dir * (8192ull * 2048ull);
#pragma unroll
    for (int i = 0; i < 8; i++) {
        int m = m0 + ty * 8 + i;
#pragma unroll
        for (int j = 0; j < 8; j += 4) {
            int n = n0 + tx * 8 + j;
            float4 v;
            v.x = acc[i][j + 0] + bias[n + 0];
            v.y = acc[i][j + 1] + bias[n + 1];
            v.z = acc[i][j + 2] + bias[n + 2];
            v.w = acc[i][j + 3] + bias[n + 3];
            *(float4*)&out[(size_t)m * 2048 + n] = v;
        }
    }
}

// ================= K2: persistent BiLSTM recurrence =================
// 128 CTAs (64 per direction) x 128 threads. CTA owns 8 hidden units (32 gate cols).
// Thread = (kslice[2], u_local[8], bgrp[8]); tile = 4 batch x 4 gates, K split in 2.
__global__ __launch_bounds__(128, 1) void lstm_kernel(
    const float* __restrict__ rf, const float* __restrict__ rb)
{
    const int bx  = blockIdx.x;       // 0..127
    const int dir = bx >> 6;
    const int u0  = (bx & 63) * 8;
    const int tid = threadIdx.x;
    const int kslice = tid >> 6;
    const int ul = (tid >> 3) & 7;
    const int bg = tid & 7;
    const int b0 = bg * 4;
    const int uu = u0 + ul;

    extern __shared__ float smem[];
    float* w_s = smem;            // [32 cols][512], k4 ^= (c>>2)
    float* h_s = smem + 16384;    // [32 b][512],  k4 ^= (b>>2)
    float* red = smem + 32768;    // [64][16]

    const float* __restrict__ rec = dir ? rb : rf;
    // Load this CTA's 32 gate-columns of rec into smem (swizzled, once).
    for (int i = tid; i < 16384; i += 128) {
        int k = i >> 5, c = i & 31;                 // c = u_local*4 + gate
        int colg = (c & 3) * 512 + u0 + (c >> 2);   // gate*512 + unit
        w_s[c * 512 + 4 * ((k >> 2) ^ (c >> 2)) + (k & 3)] = rec[(size_t)k * 2048 + colg];
    }

    const float* __restrict__ xz = g_xz + (size_t)dir * (8192ull * 2048ull);
    float* hbase = g_h + dir * 32768;     // two 16384-float buffers
    float c_st[4] = {0.f, 0.f, 0.f, 0.f};
    __syncthreads();

    for (int t = 0; t < 256; t++) {
        const int txi = dir ? (255 - t) : t;

        float xzv[4][4];
        if (kslice == 0) {
#pragma unroll
            for (int i = 0; i < 4; i++) {
                size_t base = ((size_t)(b0 + i) * 256 + txi) * 2048;
#pragma unroll
                for (int g = 0; g < 4; g++)
                    xzv[i][g] = xz[base + g * 512 + uu];
            }
        }

        if (t > 0) {
            const float4* h4 = (const float4*)(hbase + ((t + 1) & 1) * 16384);
#pragma unroll 4
            for (int i = tid; i < 4096; i += 128) {
                float4 v = h4[i];
                int b = i >> 7, k4 = i & 127;
                *(float4*)&h_s[b * 512 + 4 * (k4 ^ ((b >> 2) & 7))] = v;
            }
        }
        __syncthreads();

        float acc[4][4];
#pragma unroll
        for (int i = 0; i < 4; i++)
#pragma unroll
            for (int g = 0; g < 4; g++) acc[i][g] = 0.f;

        if (t > 0) {
#pragma unroll 2
            for (int kc = 0; kc < 64; kc++) {
                int k4 = (kslice << 6) + kc;
                float4 wv[4];
                int wk = 4 * (k4 ^ ul);
#pragma unroll
                for (int g = 0; g < 4; g++)
                    wv[g] = *(const float4*)&w_s[(ul * 4 + g) * 512 + wk];
                int hk = 4 * (k4 ^ bg);
#pragma unroll
                for (int i = 0; i < 4; i++) {
                    float4 hv = *(const float4*)&h_s[(b0 + i) * 512 + hk];
#pragma unroll
                    for (int g = 0; g < 4; g++) {
                        acc[i][g] = fmaf(hv.x, wv[g].x, acc[i][g]);
                        acc[i][g] = fmaf(hv.y, wv[g].y, acc[i][g]);
                        acc[i][g] = fmaf(hv.z, wv[g].z, acc[i][g]);
                        acc[i][g] = fmaf(hv.w, wv[g].w, acc[i][g]);
                    }
                }
            }
        }

        if (kslice == 1) {
            float* r = &red[(tid - 64) * 16];
#pragma unroll
            for (int i = 0; i < 4; i++)
#pragma unroll
                for (int g = 0; g < 4; g++) r[i * 4 + g] = acc[i][g];
        }
        __syncthreads();

        if (kslice == 0) {
            const float* r = &red[tid * 16];
            float* hw = hbase + (t & 1) * 16384;
#pragma unroll
            for (int i = 0; i < 4; i++) {
                float zi = xzv[i][0] + acc[i][0] + r[i * 4 + 0];
                float zf = xzv[i][1] + acc[i][1] + r[i * 4 + 1];
                float zg = xzv[i][2] + acc[i][2] + r[i * 4 + 2];
                float zo = xzv[i][3] + acc[i][3] + r[i * 4 + 3];
                float ig = 1.f / (1.f + __expf(-zi));
                float fg = 1.f / (1.f + __expf(-zf));
                float gg = tanhf(zg);
                float og = 1.f / (1.f + __expf(-zo));
                c_st[i] = fmaf(fg, c_st[i], ig * gg);
                float h = og * tanhf(c_st[i]);
                int b = b0 + i;
                hw[b * 512 + uu] = h;
                g_hs[((size_t)b * 256 + txi) * 1024 + dir * 512 + uu] = h;
            }
        }
        grid_barrier(128);
    }
}

// ================= K3: dense + SELU =================
// warp per (b,t) row: logits = selu(hs @ W + b) -> d_out+1
__global__ __launch_bounds__(256) void dense_kernel(
    const float* __restrict__ W, const float* __restrict__ bias, float* __restrict__ logits)
{
    int warp = (blockIdx.x * blockDim.x + threadIdx.x) >> 5;
    int lane = threadIdx.x & 31;
    if (warp >= 8192) return;
    const float4* h4 = (const float4*)(g_hs + (size_t)warp * 1024);
    float acc = (lane < 25) ? bias[lane] : 0.f;
#pragma unroll 4
    for (int k4 = 0; k4 < 256; k4++) {
        float4 h = h4[k4];
        int k = k4 * 4;
        if (lane < 25) {
            acc = fmaf(h.x, W[(k + 0) * 25 + lane], acc);
            acc = fmaf(h.y, W[(k + 1) * 25 + lane], acc);
            acc = fmaf(h.z, W[(k + 2) * 25 + lane], acc);
            acc = fmaf(h.w, W[(k + 3) * 25 + lane], acc);
        }
    }
    if (lane < 25) {
        float y = acc;
        y = 1.0507009873554805f * (y > 0.f ? y : 1.6732632423543772f * (__expf(y) - 1.f));
        logits[(size_t)warp * 25 + lane] = y;
    }
}

// ================= K4: CRF NLL per batch =================
__global__ __launch_bounds__(32) void crf_kernel(
    const float* __restrict__ logits, const int* __restrict__ tags,
    const int* __restrict__ lens, const float* __restrict__ trans)
{
    const int b = blockIdx.x;
    const int j = threadIdx.x;   // 32 lanes, 25 active for alpha
    __shared__ float tr[625];
    __shared__ float alpha[25];
    for (int i = j; i < 625; i += 32) tr[i] = trans[i];
    int len = lens[b];
    if (len < 1) len = 1;
    if (len > 256) len = 256;
    const float* lg = logits + (size_t)b * 256 * 25;
    if (j < 25) alpha[j] = lg[j];
    __syncthreads();

    for (int t = 1; t < 256; t++) {
        float nv = 0.f;
        if (j < 25) {
            float m = -1e30f;
#pragma unroll
            for (int i = 0; i < 25; i++) m = fmaxf(m, alpha[i] + tr[i * 25 + j]);
            float s = 0.f;
#pragma unroll
            for (int i = 0; i < 25; i++) s += __expf(alpha[i] + tr[i * 25 + j] - m);
            nv = m + __logf(s) + lg[t * 25 + j];
        }
        __syncthreads();
        if (j < 25 && t < len) alpha[j] = nv;
        __syncthreads();
    }

    // log_z = logsumexp(alpha)
    float a = (j < 25) ? alpha[j] : -1e30f;
    float m = a;
#pragma unroll
    for (int o = 16; o > 0; o >>= 1) m = fmaxf(m, __shfl_xor_sync(0xffffffffu, m, o));
    float e = (j < 25) ? __expf(a - m) : 0.f;
#pragma unroll
    for (int o = 16; o > 0; o >>= 1) e += __shfl_xor_sync(0xffffffffu, e, o);
    float logz = m + __logf(e);

    // unary + binary scores
    const int* tg = tags + (size_t)b * 256;
    float us = 0.f, bs = 0.f;
    for (int t = j; t < 256; t += 32) {
        if (t < len) {
            us += lg[t * 25 + tg[t]];
            if (t >= 1) bs += tr[tg[t - 1] * 25 + tg[t]];
        }
    }
#pragma unroll
    for (int o = 16; o > 0; o >>= 1) {
        us += __shfl_xor_sync(0xffffffffu, us, o);
        bs += __shfl_xor_sync(0xffffffffu, bs, o);
    }
    if (j == 0) g_nll[b] = -(us + bs - logz);
}

// ================= K5: loss = mean(nll) =================
__global__ __launch_bounds__(32) void loss_kernel(float* __restrict__ out)
{
    float v = g_nll[threadIdx.x];
#pragma unroll
    for (int o = 16; o > 0; o >>= 1) v += __shfl_xor_sync(0xffffffffu, v, o);
    if (threadIdx.x == 0) out[0] = v * (1.f / 32.f);
}

// ================= launcher =================
extern "C" void kernel_launch(void* const* d_in, const int* in_sizes, int n_in,
                              void* d_out, int out_size)
{
    const float* x     = (const float*)d_in[0];
    const int*   tags  = (const int*)d_in[1];
    const int*   lens  = (const int*)d_in[2];
    const float* kf    = (const float*)d_in[3];
    const float* rf    = (const float*)d_in[4];
    const float* bf    = (const float*)d_in[5];
    const float* kb    = (const float*)d_in[6];
    const float* rb    = (const float*)d_in[7];
    const float* bb    = (const float*)d_in[8];
    const float* dw    = (const float*)d_in[9];
    const float* db    = (const float*)d_in[10];
    const float* trans = (const float*)d_in[11];
    float* out = (float*)d_out;

    (void)in_sizes; (void)n_in; (void)out_size;

    // K1: input projections for both directions
    dim3 g1(32, 64);
    xz_gemm_kernel<<<g1, 256>>>(x, kf, bf, kb, bb);

    // K2: persistent recurrence (needs >48KB dynamic smem)
    const size_t smem = (16384 + 16384 + 1024) * sizeof(float);
    cudaFuncSetAttribute(lstm_kernel, cudaFuncAttributeMaxDynamicSharedMemorySize, (int)smem);
    lstm_kernel<<<128, 128, smem>>>(rf, rb);

    // K3: dense + SELU -> logits live at d_out+1
    dense_kernel<<<1024, 256>>>(dw, db, out + 1);

    // K4: CRF per batch
    crf_kernel<<<32, 32>>>(out + 1, tags, lens, trans);

    // K5: mean loss -> d_out[0]
    loss_kernel<<<1, 32>>>(out);
}

// round 4
// speedup vs baseline: 1.1679x; 1.1679x over previous
#include <cuda_runtime.h>
#include <cstdint>
#include <cstddef>

// Problem dims: B=32, T=256, D=768, H=512, 4H=2048, N=25
// Inputs: 0 emb[32,256,768] 1 targets[32,256] 2 seq_lens[32]
//  3 k_fwd[768,2048] 4 r_fwd[512,2048] 5 b_fwd[2048]
//  6 k_bwd[768,2048] 7 r_bwd[512,2048] 8 b_bwd[2048]
//  9 dense_w[1024,25] 10 dense_b[25] 11 transitions[25,25]
// Output: d_out[0]=loss, d_out[1..]=logits[32,256,25]

// ---------------- scratch ----------------
__device__ __align__(16) float g_xz[2ull * 8192ull * 2048ull];   // xz per direction
__device__ __align__(16) float g_wT[2ull * 2048ull * 768ull];    // transposed input weights
__device__ __align__(16) float g_hs[8192ull * 1024ull];          // [row][fwd 512 | bwd 512]
__device__ __align__(16) float g_h[2 * 2 * 32 * 512];            // [dir][buf][b][u]
__device__ float g_nll[32];
__device__ unsigned g_bar_count = 0;
__device__ volatile unsigned g_bar_gen = 0;

// ---------------- grid barrier ----------------
__device__ __forceinline__ void grid_barrier(unsigned nblocks) {
    __threadfence();
    __syncthreads();
    if (threadIdx.x == 0) {
        unsigned gen = g_bar_gen;
        __threadfence();
        unsigned t = atomicAdd(&g_bar_count, 1u);
        if (t == nblocks - 1u) {
            atomicExch(&g_bar_count, 0u);
            __threadfence();
            g_bar_gen = gen + 1u;
        } else {
            while (g_bar_gen == gen) { __nanosleep(64); }
        }
        __threadfence();
    }
    __syncthreads();
}

__device__ __forceinline__ float to_tf32(float x) {
    uint32_t r;
    asm("cvt.rna.tf32.f32 %0, %1;" : "=r"(r) : "f"(x));
    return __uint_as_float(r);
}

__device__ __forceinline__ void mma_tf32(float c[4], const uint32_t a[4], const uint32_t b[2]) {
    asm volatile(
        "mma.sync.aligned.m16n8k8.row.col.f32.tf32.tf32.f32 "
        "{%0,%1,%2,%3}, {%4,%5,%6,%7}, {%8,%9}, {%0,%1,%2,%3};"
        : "+f"(c[0]), "+f"(c[1]), "+f"(c[2]), "+f"(c[3])
        : "r"(a[0]), "r"(a[1]), "r"(a[2]), "r"(a[3]),
          "r"(b[0]), "r"(b[1]));
}

// ================= K0: transpose input weights -> g_wT[dir][n][k] =================
__global__ __launch_bounds__(256) void transpose_w(
    const float* __restrict__ kf, const float* __restrict__ kb)
{
    __shared__ float t[32][33];
    const int dir = blockIdx.z;
    const float* __restrict__ w = dir ? kb : kf;
    const int kb0 = blockIdx.y * 32;
    const int nb0 = blockIdx.x * 32;
    const int tx = threadIdx.x & 31, ty = threadIdx.x >> 5;
#pragma unroll
    for (int r = 0; r < 32; r += 8)
        t[ty + r][tx] = w[(size_t)(kb0 + ty + r) * 2048 + nb0 + tx];
    __syncthreads();
#pragma unroll
    for (int r = 0; r < 32; r += 8)
        g_wT[((size_t)dir * 2048 + nb0 + ty + r) * 768 + kb0 + tx] = t[tx][ty + r];
}

// ================= K1: xz = x @ K + b via mma.sync tf32 =================
// Block tile 128x128, 8 warps (4x2), warp tile 32x64, K chunk 16, double buffered.
__global__ __launch_bounds__(256, 2) void xz_gemm_mma(
    const float* __restrict__ x,
    const float* __restrict__ bf, const float* __restrict__ bb)
{
    __shared__ float As[2][128][20];   // [m][k], stride 20 -> conflict-free frag loads
    __shared__ float Bs[2][16][136];   // [k][n], stride 136 -> conflict-free frag loads

    const int m0 = blockIdx.y * 128;
    const int nb = blockIdx.x;            // 0..31
    const int dir = nb >> 4;
    const int n0 = (nb & 15) * 128;
    const float* __restrict__ wT = g_wT + (size_t)dir * 2048ull * 768ull;
    const float* __restrict__ bias = dir ? bb : bf;

    const int tid = threadIdx.x;
    const int warp = tid >> 5, lane = tid & 31;
    const int warpM = warp >> 1, warpN = warp & 1;   // 4 x 2
    const int mbase = warpM * 32, nbase = warpN * 64;
    const int gid = lane >> 2, tig = lane & 3;

    // loader mapping: 2 threads per row, 8 floats each
    const int la_m = tid >> 1;
    const int la_k = (tid & 1) * 8;

    float c[2][8][4];
#pragma unroll
    for (int mi = 0; mi < 2; mi++)
#pragma unroll
        for (int ni = 0; ni < 8; ni++)
#pragma unroll
            for (int q = 0; q < 4; q++) c[mi][ni][q] = 0.f;

    // prologue: chunk 0 -> buf 0
    {
        float4 a0 = *(const float4*)&x[(size_t)(m0 + la_m) * 768 + la_k];
        float4 a1 = *(const float4*)&x[(size_t)(m0 + la_m) * 768 + la_k + 4];
        As[0][la_m][la_k + 0] = to_tf32(a0.x); As[0][la_m][la_k + 1] = to_tf32(a0.y);
        As[0][la_m][la_k + 2] = to_tf32(a0.z); As[0][la_m][la_k + 3] = to_tf32(a0.w);
        As[0][la_m][la_k + 4] = to_tf32(a1.x); As[0][la_m][la_k + 5] = to_tf32(a1.y);
        As[0][la_m][la_k + 6] = to_tf32(a1.z); As[0][la_m][la_k + 7] = to_tf32(a1.w);
        float4 b0 = *(const float4*)&wT[(size_t)(n0 + la_m) * 768 + la_k];
        float4 b1 = *(const float4*)&wT[(size_t)(n0 + la_m) * 768 + la_k + 4];
        Bs[0][la_k + 0][la_m] = to_tf32(b0.x); Bs[0][la_k + 1][la_m] = to_tf32(b0.y);
        Bs[0][la_k + 2][la_m] = to_tf32(b0.z); Bs[0][la_k + 3][la_m] = to_tf32(b0.w);
        Bs[0][la_k + 4][la_m] = to_tf32(b1.x); Bs[0][la_k + 5][la_m] = to_tf32(b1.y);
        Bs[0][la_k + 6][la_m] = to_tf32(b1.z); Bs[0][la_k + 7][la_m] = to_tf32(b1.w);
    }
    __syncthreads();

    int buf = 0;
    for (int kt = 0; kt < 48; kt++) {
        float4 pa0, pa1, pb0, pb1;
        if (kt < 47) {
            const int k0 = (kt + 1) * 16;
            pa0 = *(const float4*)&x[(size_t)(m0 + la_m) * 768 + k0 + la_k];
            pa1 = *(const float4*)&x[(size_t)(m0 + la_m) * 768 + k0 + la_k + 4];
            pb0 = *(const float4*)&wT[(size_t)(n0 + la_m) * 768 + k0 + la_k];
            pb1 = *(const float4*)&wT[(size_t)(n0 + la_m) * 768 + k0 + la_k + 4];
        }

        // compute on buf
#pragma unroll
        for (int ks = 0; ks < 2; ks++) {
            const int kk = ks * 8;
            uint32_t af[2][4];
#pragma unroll
            for (int mi = 0; mi < 2; mi++) {
                const int r = mbase + mi * 16 + gid;
                af[mi][0] = __float_as_uint(As[buf][r][kk + tig]);
                af[mi][1] = __float_as_uint(As[buf][r + 8][kk + tig]);
                af[mi][2] = __float_as_uint(As[buf][r][kk + tig + 4]);
                af[mi][3] = __float_as_uint(As[buf][r + 8][kk + tig + 4]);
            }
            uint32_t bfr[8][2];
#pragma unroll
            for (int ni = 0; ni < 8; ni++) {
                const int col = nbase + ni * 8 + gid;
                bfr[ni][0] = __float_as_uint(Bs[buf][kk + tig][col]);
                bfr[ni][1] = __float_as_uint(Bs[buf][kk + tig + 4][col]);
            }
#pragma unroll
            for (int mi = 0; mi < 2; mi++)
#pragma unroll
                for (int ni = 0; ni < 8; ni++)
                    mma_tf32(c[mi][ni], af[mi], bfr[ni]);
        }

        if (kt < 47) {
            const int nbuf = buf ^ 1;
            As[nbuf][la_m][la_k + 0] = to_tf32(pa0.x); As[nbuf][la_m][la_k + 1] = to_tf32(pa0.y);
            As[nbuf][la_m][la_k + 2] = to_tf32(pa0.z); As[nbuf][la_m][la_k + 3] = to_tf32(pa0.w);
            As[nbuf][la_m][la_k + 4] = to_tf32(pa1.x); As[nbuf][la_m][la_k + 5] = to_tf32(pa1.y);
            As[nbuf][la_m][la_k + 6] = to_tf32(pa1.z); As[nbuf][la_m][la_k + 7] = to_tf32(pa1.w);
            Bs[nbuf][la_k + 0][la_m] = to_tf32(pb0.x); Bs[nbuf][la_k + 1][la_m] = to_tf32(pb0.y);
            Bs[nbuf][la_k + 2][la_m] = to_tf32(pb0.z); Bs[nbuf][la_k + 3][la_m] = to_tf32(pb0.w);
            Bs[nbuf][la_k + 4][la_m] = to_tf32(pb1.x); Bs[nbuf][la_k + 5][la_m] = to_tf32(pb1.y);
            Bs[nbuf][la_k + 6][la_m] = to_tf32(pb1.z); Bs[nbuf][la_k + 7][la_m] = to_tf32(pb1.w);
        }
        __syncthreads();
        buf ^= 1;
    }

    // epilogue
    float* outp = g_xz + (size_t)dir * (8192ull * 2048ull);
#pragma unroll
    for (int mi = 0; mi < 2; mi++) {
        const int r0 = m0 + mbase + mi * 16 + gid;
#pragma unroll
        for (int ni = 0; ni < 8; ni++) {
            const int cc = n0 + nbase + ni * 8 + tig * 2;
            float2 b2 = *(const float2*)&bias[cc];
            float2 v0 = { c[mi][ni][0] + b2.x, c[mi][ni][1] + b2.y };
            float2 v1 = { c[mi][ni][2] + b2.x, c[mi][ni][3] + b2.y };
            *(float2*)&outp[(size_t)r0 * 2048 + cc] = v0;
            *(float2*)&outp[(size_t)(r0 + 8) * 2048 + cc] = v1;
        }
    }
}

// ================= K2: persistent BiLSTM recurrence (fp32) =================
__global__ __launch_bounds__(128, 1) void lstm_kernel(
    const float* __restrict__ rf, const float* __restrict__ rb)
{
    const int bx  = blockIdx.x;       // 0..127
    const int dir = bx >> 6;
    const int u0  = (bx & 63) * 8;
    const int tid = threadIdx.x;
    const int kslice = tid >> 6;
    const int ul = (tid >> 3) & 7;
    const int bg = tid & 7;
    const int b0 = bg * 4;
    const int uu = u0 + ul;

    extern __shared__ float smem[];
    float* w_s = smem;            // [32 cols][512], swizzled
    float* h_s = smem + 16384;    // [32 b][512], swizzled
    float* red = smem + 32768;    // [64][16]

    const float* __restrict__ rec = dir ? rb : rf;
    for (int i = tid; i < 16384; i += 128) {
        int k = i >> 5, c = i & 31;
        int colg = (c & 3) * 512 + u0 + (c >> 2);
        w_s[c * 512 + 4 * ((k >> 2) ^ (c >> 2)) + (k & 3)] = rec[(size_t)k * 2048 + colg];
    }

    const float* __restrict__ xz = g_xz + (size_t)dir * (8192ull * 2048ull);
    float* hbase = g_h + dir * 32768;
    float c_st[4] = {0.f, 0.f, 0.f, 0.f};
    __syncthreads();

    for (int t = 0; t < 256; t++) {
        const int txi = dir ? (255 - t) : t;

        float xzv[4][4];
        if (kslice == 0) {
#pragma unroll
            for (int i = 0; i < 4; i++) {
                size_t base = ((size_t)(b0 + i) * 256 + txi) * 2048;
#pragma unroll
                for (int g = 0; g < 4; g++)
                    xzv[i][g] = xz[base + g * 512 + uu];
            }
        }

        if (t > 0) {
            const float4* h4 = (const float4*)(hbase + ((t + 1) & 1) * 16384);
#pragma unroll 4
            for (int i = tid; i < 4096; i += 128) {
                float4 v = h4[i];
                int b = i >> 7, k4 = i & 127;
                *(float4*)&h_s[b * 512 + 4 * (k4 ^ ((b >> 2) & 7))] = v;
            }
        }
        __syncthreads();

        float acc[4][4];
#pragma unroll
        for (int i = 0; i < 4; i++)
#pragma unroll
            for (int g = 0; g < 4; g++) acc[i][g] = 0.f;

        if (t > 0) {
#pragma unroll 2
            for (int kc = 0; kc < 64; kc++) {
                int k4 = (kslice << 6) + kc;
                float4 wv[4];
                int wk = 4 * (k4 ^ ul);
#pragma unroll
                for (int g = 0; g < 4; g++)
                    wv[g] = *(const float4*)&w_s[(ul * 4 + g) * 512 + wk];
                int hk = 4 * (k4 ^ bg);
#pragma unroll
                for (int i = 0; i < 4; i++) {
                    float4 hv = *(const float4*)&h_s[(b0 + i) * 512 + hk];
#pragma unroll
                    for (int g = 0; g < 4; g++) {
                        acc[i][g] = fmaf(hv.x, wv[g].x, acc[i][g]);
                        acc[i][g] = fmaf(hv.y, wv[g].y, acc[i][g]);
                        acc[i][g] = fmaf(hv.z, wv[g].z, acc[i][g]);
                        acc[i][g] = fmaf(hv.w, wv[g].w, acc[i][g]);
                    }
                }
            }
        }

        if (kslice == 1) {
            float* r = &red[(tid - 64) * 16];
#pragma unroll
            for (int i = 0; i < 4; i++)
#pragma unroll
                for (int g = 0; g < 4; g++) r[i * 4 + g] = acc[i][g];
        }
        __syncthreads();

        if (kslice == 0) {
            const float* r = &red[tid * 16];
            float* hw = hbase + (t & 1) * 16384;
#pragma unroll
            for (int i = 0; i < 4; i++) {
                float zi = xzv[i][0] + acc[i][0] + r[i * 4 + 0];
                float zf = xzv[i][1] + acc[i][1] + r[i * 4 + 1];
                float zg = xzv[i][2] + acc[i][2] + r[i * 4 + 2];
                float zo = xzv[i][3] + acc[i][3] + r[i * 4 + 3];
                float ig = 1.f / (1.f + __expf(-zi));
                float fg = 1.f / (1.f + __expf(-zf));
                float gg = tanhf(zg);
                float og = 1.f / (1.f + __expf(-zo));
                c_st[i] = fmaf(fg, c_st[i], ig * gg);
                float h = og * tanhf(c_st[i]);
                int b = b0 + i;
                hw[b * 512 + uu] = h;
                g_hs[((size_t)b * 256 + txi) * 1024 + dir * 512 + uu] = h;
            }
        }
        grid_barrier(128);
    }
}

// ================= K3: dense + SELU =================
__global__ __launch_bounds__(256) void dense_kernel(
    const float* __restrict__ W, const float* __restrict__ bias, float* __restrict__ logits)
{
    int warp = (blockIdx.x * blockDim.x + threadIdx.x) >> 5;
    int lane = threadIdx.x & 31;
    if (warp >= 8192) return;
    const float4* h4 = (const float4*)(g_hs + (size_t)warp * 1024);
    float acc = (lane < 25) ? bias[lane] : 0.f;
#pragma unroll 4
    for (int k4 = 0; k4 < 256; k4++) {
        float4 h = h4[k4];
        int k = k4 * 4;
        if (lane < 25) {
            acc = fmaf(h.x, W[(k + 0) * 25 + lane], acc);
            acc = fmaf(h.y, W[(k + 1) * 25 + lane], acc);
            acc = fmaf(h.z, W[(k + 2) * 25 + lane], acc);
            acc = fmaf(h.w, W[(k + 3) * 25 + lane], acc);
        }
    }
    if (lane < 25) {
        float y = acc;
        y = 1.0507009873554805f * (y > 0.f ? y : 1.6732632423543772f * (__expf(y) - 1.f));
        logits[(size_t)warp * 25 + lane] = y;
    }
}

// ================= K4: CRF NLL per batch (register alpha + shfl) =================
__global__ __launch_bounds__(32) void crf_kernel(
    const float* __restrict__ logits, const int* __restrict__ tags,
    const int* __restrict__ lens, const float* __restrict__ trans)
{
    const int b = blockIdx.x;
    const int j = threadIdx.x;
    __shared__ float tr[625];
    for (int i = j; i < 625; i += 32) tr[i] = trans[i];
    int len = lens[b];
    if (len < 1) len = 1;
    if (len > 256) len = 256;
    const float* lg = logits + (size_t)b * 256 * 25;
    __syncthreads();

    float a = (j < 25) ? lg[j] : -1e30f;
    for (int t = 1; t < 256; t++) {
        float m = -1e30f;
        float v[25];
#pragma unroll
        for (int i = 0; i < 25; i++) {
            v[i] = __shfl_sync(0xffffffffu, a, i) + tr[i * 25 + j];
            m = fmaxf(m, v[i]);
        }
        float s = 0.f;
#pragma unroll
        for (int i = 0; i < 25; i++) s += __expf(v[i] - m);
        float nv = m + __logf(s) + lg[t * 25 + j];
        if (j < 25 && t < len) a = nv;
    }

    float m = a;
#pragma unroll
    for (int o = 16; o > 0; o >>= 1) m = fmaxf(m, __shfl_xor_sync(0xffffffffu, m, o));
    float e = (j < 25) ? __expf(a - m) : 0.f;
#pragma unroll
    for (int o = 16; o > 0; o >>= 1) e += __shfl_xor_sync(0xffffffffu, e, o);
    float logz = m + __logf(e);

    const int* tg = tags + (size_t)b * 256;
    float us = 0.f, bs = 0.f;
    for (int t = j; t < 256; t += 32) {
        if (t < len) {
            us += lg[t * 25 + tg[t]];
            if (t >= 1) bs += tr[tg[t - 1] * 25 + tg[t]];
        }
    }
#pragma unroll
    for (int o = 16; o > 0; o >>= 1) {
        us += __shfl_xor_sync(0xffffffffu, us, o);
        bs += __shfl_xor_sync(0xffffffffu, bs, o);
    }
    if (j == 0) g_nll[b] = -(us + bs - logz);
}

// ================= K5: loss = mean(nll) =================
__global__ __launch_bounds__(32) void loss_kernel(float* __restrict__ out)
{
    float v = g_nll[threadIdx.x];
#pragma unroll
    for (int o = 16; o > 0; o >>= 1) v += __shfl_xor_sync(0xffffffffu, v, o);
    if (threadIdx.x == 0) out[0] = v * (1.f / 32.f);
}

// ================= launcher =================
extern "C" void kernel_launch(void* const* d_in, const int* in_sizes, int n_in,
                              void* d_out, int out_size)
{
    const float* x     = (const float*)d_in[0];
    const int*   tags  = (const int*)d_in[1];
    const int*   lens  = (const int*)d_in[2];
    const float* kf    = (const float*)d_in[3];
    const float* rf    = (const float*)d_in[4];
    const float* bf    = (const float*)d_in[5];
    const float* kb    = (const float*)d_in[6];
    const float* rb    = (const float*)d_in[7];
    const float* bb    = (const float*)d_in[8];
    const float* dw    = (const float*)d_in[9];
    const float* db    = (const float*)d_in[10];
    const float* trans = (const float*)d_in[11];
    float* out = (float*)d_out;

    (void)in_sizes; (void)n_in; (void)out_size;

    // K0: transpose input weights
    dim3 gt(64, 24, 2);
    transpose_w<<<gt, 256>>>(kf, kb);

    // K1: tf32 mma.sync input projections
    dim3 g1(32, 64);
    xz_gemm_mma<<<g1, 256>>>(x, bf, bb);

    // K2: persistent recurrence
    const size_t smem = (16384 + 16384 + 1024) * sizeof(float);
    cudaFuncSetAttribute(lstm_kernel, cudaFuncAttributeMaxDynamicSharedMemorySize, (int)smem);
    lstm_kernel<<<128, 128, smem>>>(rf, rb);

    // K3: dense + SELU
    dense_kernel<<<1024, 256>>>(dw, db, out + 1);

    // K4: CRF per batch
    crf_kernel<<<32, 32>>>(out + 1, tags, lens, trans);

    // K5: mean loss
    loss_kernel<<<1, 32>>>(out);
}

// round 5
// speedup vs baseline: 1.4734x; 1.2615x over previous
#include <cuda_runtime.h>
#include <cstdint>
#include <cstddef>

// Problem dims: B=32, T=256, D=768, H=512, 4H=2048, N=25
// Output: d_out[0]=loss, d_out[1..]=logits[32,256,25]

// ---------------- scratch ----------------
__device__ __align__(16) float g_xz[2ull * 8192ull * 2048ull];   // [dir][t*32+b][2048]
__device__ __align__(16) float g_wT[2ull * 2048ull * 768ull];    // transposed input weights
__device__ __align__(16) float g_hs[8192ull * 1024ull];          // [b*256+t][fwd 512 | bwd 512]
__device__ __align__(16) float g_h[2 * 2 * 32 * 512];            // [dir][buf][b][u]
__device__ float g_nll[32];
__device__ volatile int g_flags[128];
__device__ volatile int g_gen2;

// ---------------- fast grid barrier (parallel arrivals, single release) ----------------
__device__ __forceinline__ void fast_barrier(int bx, int tid, int target) {
    __threadfence();
    __syncthreads();
    if (bx == 0) {
        if (tid > 0 && tid < 128) {
            while (g_flags[tid] < target) { }
        }
        __syncthreads();
        if (tid == 0) { g_flags[0] = target; __threadfence(); g_gen2 = target; }
    } else {
        if (tid == 0) g_flags[bx] = target;
    }
    if (tid == 0) { while (g_gen2 < target) { } }
    __syncthreads();
    __threadfence();
}

__device__ __forceinline__ float to_tf32(float x) {
    uint32_t r;
    asm("cvt.rna.tf32.f32 %0, %1;" : "=r"(r) : "f"(x));
    return __uint_as_float(r);
}

__device__ __forceinline__ void mma_tf32(float c[4], const uint32_t a[4], const uint32_t b[2]) {
    asm volatile(
        "mma.sync.aligned.m16n8k8.row.col.f32.tf32.tf32.f32 "
        "{%0,%1,%2,%3}, {%4,%5,%6,%7}, {%8,%9}, {%0,%1,%2,%3};"
        : "+f"(c[0]), "+f"(c[1]), "+f"(c[2]), "+f"(c[3])
        : "r"(a[0]), "r"(a[1]), "r"(a[2]), "r"(a[3]),
          "r"(b[0]), "r"(b[1]));
}

// ================= K0: transpose input weights -> g_wT[dir][n][k] =================
__global__ __launch_bounds__(256) void transpose_w(
    const float* __restrict__ kf, const float* __restrict__ kb)
{
    __shared__ float t[32][33];
    const int dir = blockIdx.z;
    const float* __restrict__ w = dir ? kb : kf;
    const int kb0 = blockIdx.y * 32;
    const int nb0 = blockIdx.x * 32;
    const int tx = threadIdx.x & 31, ty = threadIdx.x >> 5;
#pragma unroll
    for (int r = 0; r < 32; r += 8)
        t[ty + r][tx] = w[(size_t)(kb0 + ty + r) * 2048 + nb0 + tx];
    __syncthreads();
#pragma unroll
    for (int r = 0; r < 32; r += 8)
        g_wT[((size_t)dir * 2048 + nb0 + ty + r) * 768 + kb0 + tx] = t[tx][ty + r];
}

// ================= K1: xz = x @ K + b via mma.sync tf32 =================
// Block tile 128x128, 8 warps (4x2), warp tile 32x64, K chunk 16, double buffered.
// Output layout: g_xz[dir][(t*32+b)][col] so each timestep is a contiguous slab.
__global__ __launch_bounds__(256, 2) void xz_gemm_mma(
    const float* __restrict__ x,
    const float* __restrict__ bf, const float* __restrict__ bb)
{
    __shared__ float As[2][128][20];
    __shared__ float Bs[2][16][136];

    const int m0 = blockIdx.y * 128;
    const int nb = blockIdx.x;            // 0..31
    const int dir = nb >> 4;
    const int n0 = (nb & 15) * 128;
    const float* __restrict__ wT = g_wT + (size_t)dir * 2048ull * 768ull;
    const float* __restrict__ bias = dir ? bb : bf;

    const int tid = threadIdx.x;
    const int warp = tid >> 5, lane = tid & 31;
    const int warpM = warp >> 1, warpN = warp & 1;
    const int mbase = warpM * 32, nbase = warpN * 64;
    const int gid = lane >> 2, tig = lane & 3;

    const int la_m = tid >> 1;
    const int la_k = (tid & 1) * 8;

    float c[2][8][4];
#pragma unroll
    for (int mi = 0; mi < 2; mi++)
#pragma unroll
        for (int ni = 0; ni < 8; ni++)
#pragma unroll
            for (int q = 0; q < 4; q++) c[mi][ni][q] = 0.f;

    {
        float4 a0 = *(const float4*)&x[(size_t)(m0 + la_m) * 768 + la_k];
        float4 a1 = *(const float4*)&x[(size_t)(m0 + la_m) * 768 + la_k + 4];
        As[0][la_m][la_k + 0] = to_tf32(a0.x); As[0][la_m][la_k + 1] = to_tf32(a0.y);
        As[0][la_m][la_k + 2] = to_tf32(a0.z); As[0][la_m][la_k + 3] = to_tf32(a0.w);
        As[0][la_m][la_k + 4] = to_tf32(a1.x); As[0][la_m][la_k + 5] = to_tf32(a1.y);
        As[0][la_m][la_k + 6] = to_tf32(a1.z); As[0][la_m][la_k + 7] = to_tf32(a1.w);
        float4 b0 = *(const float4*)&wT[(size_t)(n0 + la_m) * 768 + la_k];
        float4 b1 = *(const float4*)&wT[(size_t)(n0 + la_m) * 768 + la_k + 4];
        Bs[0][la_k + 0][la_m] = to_tf32(b0.x); Bs[0][la_k + 1][la_m] = to_tf32(b0.y);
        Bs[0][la_k + 2][la_m] = to_tf32(b0.z); Bs[0][la_k + 3][la_m] = to_tf32(b0.w);
        Bs[0][la_k + 4][la_m] = to_tf32(b1.x); Bs[0][la_k + 5][la_m] = to_tf32(b1.y);
        Bs[0][la_k + 6][la_m] = to_tf32(b1.z); Bs[0][la_k + 7][la_m] = to_tf32(b1.w);
    }
    __syncthreads();

    int buf = 0;
    for (int kt = 0; kt < 48; kt++) {
        float4 pa0, pa1, pb0, pb1;
        if (kt < 47) {
            const int k0 = (kt + 1) * 16;
            pa0 = *(const float4*)&x[(size_t)(m0 + la_m) * 768 + k0 + la_k];
            pa1 = *(const float4*)&x[(size_t)(m0 + la_m) * 768 + k0 + la_k + 4];
            pb0 = *(const float4*)&wT[(size_t)(n0 + la_m) * 768 + k0 + la_k];
            pb1 = *(const float4*)&wT[(size_t)(n0 + la_m) * 768 + k0 + la_k + 4];
        }

#pragma unroll
        for (int ks = 0; ks < 2; ks++) {
            const int kk = ks * 8;
            uint32_t af[2][4];
#pragma unroll
            for (int mi = 0; mi < 2; mi++) {
                const int r = mbase + mi * 16 + gid;
                af[mi][0] = __float_as_uint(As[buf][r][kk + tig]);
                af[mi][1] = __float_as_uint(As[buf][r + 8][kk + tig]);
                af[mi][2] = __float_as_uint(As[buf][r][kk + tig + 4]);
                af[mi][3] = __float_as_uint(As[buf][r + 8][kk + tig + 4]);
            }
            uint32_t bfr[8][2];
#pragma unroll
            for (int ni = 0; ni < 8; ni++) {
                const int col = nbase + ni * 8 + gid;
                bfr[ni][0] = __float_as_uint(Bs[buf][kk + tig][col]);
                bfr[ni][1] = __float_as_uint(Bs[buf][kk + tig + 4][col]);
            }
#pragma unroll
            for (int mi = 0; mi < 2; mi++)
#pragma unroll
                for (int ni = 0; ni < 8; ni++)
                    mma_tf32(c[mi][ni], af[mi], bfr[ni]);
        }

        if (kt < 47) {
            const int nbuf = buf ^ 1;
            As[nbuf][la_m][la_k + 0] = to_tf32(pa0.x); As[nbuf][la_m][la_k + 1] = to_tf32(pa0.y);
            As[nbuf][la_m][la_k + 2] = to_tf32(pa0.z); As[nbuf][la_m][la_k + 3] = to_tf32(pa0.w);
            As[nbuf][la_m][la_k + 4] = to_tf32(pa1.x); As[nbuf][la_m][la_k + 5] = to_tf32(pa1.y);
            As[nbuf][la_m][la_k + 6] = to_tf32(pa1.z); As[nbuf][la_m][la_k + 7] = to_tf32(pa1.w);
            Bs[nbuf][la_k + 0][la_m] = to_tf32(pb0.x); Bs[nbuf][la_k + 1][la_m] = to_tf32(pb0.y);
            Bs[nbuf][la_k + 2][la_m] = to_tf32(pb0.z); Bs[nbuf][la_k + 3][la_m] = to_tf32(pb0.w);
            Bs[nbuf][la_k + 4][la_m] = to_tf32(pb1.x); Bs[nbuf][la_k + 5][la_m] = to_tf32(pb1.y);
            Bs[nbuf][la_k + 6][la_m] = to_tf32(pb1.z); Bs[nbuf][la_k + 7][la_m] = to_tf32(pb1.w);
        }
        __syncthreads();
        buf ^= 1;
    }

    // epilogue: rows remapped (b,t) -> (t*32+b)
    float* outp = g_xz + (size_t)dir * (8192ull * 2048ull);
#pragma unroll
    for (int mi = 0; mi < 2; mi++) {
        const int r0 = m0 + mbase + mi * 16 + gid;
        const int r1 = r0 + 8;
        const size_t o0 = (size_t)((r0 & 255) * 32 + (r0 >> 8)) * 2048;
        const size_t o1 = (size_t)((r1 & 255) * 32 + (r1 >> 8)) * 2048;
#pragma unroll
        for (int ni = 0; ni < 8; ni++) {
            const int cc = n0 + nbase + ni * 8 + tig * 2;
            float2 b2 = *(const float2*)&bias[cc];
            float2 v0 = { c[mi][ni][0] + b2.x, c[mi][ni][1] + b2.y };
            float2 v1 = { c[mi][ni][2] + b2.x, c[mi][ni][3] + b2.y };
            *(float2*)&outp[o0 + cc] = v0;
            *(float2*)&outp[o1 + cc] = v1;
        }
    }
}

// ================= K2: persistent BiLSTM recurrence (fp32, 256 threads) =================
// 128 CTAs (64/dir) x 256 threads. CTA owns 8 hidden units (32 gate cols).
// Thread = (kslice[4], u_local[8], bgrp[8]); tile 4 batch x 4 gates, K split 4 ways.
__global__ __launch_bounds__(256, 1) void lstm_kernel(
    const float* __restrict__ rf, const float* __restrict__ rb)
{
    const int bx  = blockIdx.x;       // 0..127
    const int dir = bx >> 6;
    const int u0  = (bx & 63) * 8;
    const int tid = threadIdx.x;
    const int kslice = tid >> 6;      // 0..3
    const int t64 = tid & 63;
    const int ul = t64 >> 3;
    const int bg = tid & 7;
    const int b0 = bg * 4;
    const int uu = u0 + ul;

    extern __shared__ float smem[];
    float* w_s = smem;            // [32 cols][512], swizzled (64KB)
    float* h_s = smem + 16384;    // [32 b][512], swizzled (64KB)
    float* red = smem + 32768;    // [3][64][17] (~13KB)

    const float* __restrict__ rec = dir ? rb : rf;
    for (int i = tid; i < 16384; i += 256) {
        int k = i >> 5, c = i & 31;
        int colg = (c & 3) * 512 + u0 + (c >> 2);
        w_s[c * 512 + 4 * ((k >> 2) ^ (c >> 2)) + (k & 3)] = rec[(size_t)k * 2048 + colg];
    }

    const float* __restrict__ xz = g_xz + (size_t)dir * (8192ull * 2048ull);
    float* hbase = g_h + dir * 32768;
    float c_st[4] = {0.f, 0.f, 0.f, 0.f};
    const int base = g_flags[bx];     // monotonic counter from previous launch (graph-replay safe)
    __syncthreads();

    for (int t = 0; t < 256; t++) {
        const int txi = dir ? (255 - t) : t;

        float xzv[4][4];
        if (kslice == 0) {
            const float* slab = xz + (size_t)txi * 32 * 2048;
#pragma unroll
            for (int i = 0; i < 4; i++) {
#pragma unroll
                for (int g = 0; g < 4; g++)
                    xzv[i][g] = slab[(b0 + i) * 2048 + g * 512 + uu];
            }
        }

        if (t > 0) {
            const float4* h4 = (const float4*)(hbase + ((t + 1) & 1) * 16384);
#pragma unroll 4
            for (int i = tid; i < 4096; i += 256) {
                float4 v = h4[i];
                int b = i >> 7, k4 = i & 127;
                *(float4*)&h_s[b * 512 + 4 * (k4 ^ ((b >> 2) & 7))] = v;
            }
        }
        __syncthreads();

        float acc[4][4];
#pragma unroll
        for (int i = 0; i < 4; i++)
#pragma unroll
            for (int g = 0; g < 4; g++) acc[i][g] = 0.f;

        if (t > 0) {
#pragma unroll 2
            for (int kc = 0; kc < 32; kc++) {
                int k4 = (kslice << 5) + kc;
                float4 wv[4];
                int wk = 4 * (k4 ^ ul);
#pragma unroll
                for (int g = 0; g < 4; g++)
                    wv[g] = *(const float4*)&w_s[(ul * 4 + g) * 512 + wk];
                int hk = 4 * (k4 ^ bg);
#pragma unroll
                for (int i = 0; i < 4; i++) {
                    float4 hv = *(const float4*)&h_s[(b0 + i) * 512 + hk];
#pragma unroll
                    for (int g = 0; g < 4; g++) {
                        acc[i][g] = fmaf(hv.x, wv[g].x, acc[i][g]);
                        acc[i][g] = fmaf(hv.y, wv[g].y, acc[i][g]);
                        acc[i][g] = fmaf(hv.z, wv[g].z, acc[i][g]);
                        acc[i][g] = fmaf(hv.w, wv[g].w, acc[i][g]);
                    }
                }
            }
        }

        if (kslice > 0) {
            float* r = &red[((kslice - 1) * 64 + t64) * 17];
#pragma unroll
            for (int i = 0; i < 4; i++)
#pragma unroll
                for (int g = 0; g < 4; g++) r[i * 4 + g] = acc[i][g];
        }
        __syncthreads();

        if (kslice == 0) {
#pragma unroll
            for (int s = 0; s < 3; s++) {
                const float* r = &red[(s * 64 + t64) * 17];
#pragma unroll
                for (int i = 0; i < 4; i++)
#pragma unroll
                    for (int g = 0; g < 4; g++) acc[i][g] += r[i * 4 + g];
            }
            float* hw = hbase + (t & 1) * 16384;
#pragma unroll
            for (int i = 0; i < 4; i++) {
                float zi = xzv[i][0] + acc[i][0];
                float zf = xzv[i][1] + acc[i][1];
                float zg = xzv[i][2] + acc[i][2];
                float zo = xzv[i][3] + acc[i][3];
                float ig = 1.f / (1.f + __expf(-zi));
                float fg = 1.f / (1.f + __expf(-zf));
                float gg = tanhf(zg);
                float og = 1.f / (1.f + __expf(-zo));
                c_st[i] = fmaf(fg, c_st[i], ig * gg);
                float h = og * tanhf(c_st[i]);
                int b = b0 + i;
                hw[b * 512 + uu] = h;
                g_hs[((size_t)b * 256 + txi) * 1024 + dir * 512 + uu] = h;
            }
        }
        fast_barrier(bx, tid, base + t + 1);
    }
}

// ================= K3: dense + SELU =================
__global__ __launch_bounds__(256) void dense_kernel(
    const float* __restrict__ W, const float* __restrict__ bias, float* __restrict__ logits)
{
    int warp = (blockIdx.x * blockDim.x + threadIdx.x) >> 5;
    int lane = threadIdx.x & 31;
    if (warp >= 8192) return;
    const float4* h4 = (const float4*)(g_hs + (size_t)warp * 1024);
    float acc = (lane < 25) ? bias[lane] : 0.f;
#pragma unroll 4
    for (int k4 = 0; k4 < 256; k4++) {
        float4 h = h4[k4];
        int k = k4 * 4;
        if (lane < 25) {
            acc = fmaf(h.x, W[(k + 0) * 25 + lane], acc);
            acc = fmaf(h.y, W[(k + 1) * 25 + lane], acc);
            acc = fmaf(h.z, W[(k + 2) * 25 + lane], acc);
            acc = fmaf(h.w, W[(k + 3) * 25 + lane], acc);
        }
    }
    if (lane < 25) {
        float y = acc;
        y = 1.0507009873554805f * (y > 0.f ? y : 1.6732632423543772f * (__expf(y) - 1.f));
        logits[(size_t)warp * 25 + lane] = y;
    }
}

// ================= K4: CRF NLL per batch (register alpha + shfl) =================
__global__ __launch_bounds__(32) void crf_kernel(
    const float* __restrict__ logits, const int* __restrict__ tags,
    const int* __restrict__ lens, const float* __restrict__ trans)
{
    const int b = blockIdx.x;
    const int j = threadIdx.x;
    __shared__ float tr[625];
    for (int i = j; i < 625; i += 32) tr[i] = trans[i];
    int len = lens[b];
    if (len < 1) len = 1;
    if (len > 256) len = 256;
    const float* lg = logits + (size_t)b * 256 * 25;
    __syncthreads();

    float a = (j < 25) ? lg[j] : -1e30f;
    for (int t = 1; t < 256; t++) {
        float m = -1e30f;
        float v[25];
#pragma unroll
        for (int i = 0; i < 25; i++) {
            v[i] = __shfl_sync(0xffffffffu, a, i) + tr[i * 25 + j];
            m = fmaxf(m, v[i]);
        }
        float s = 0.f;
#pragma unroll
        for (int i = 0; i < 25; i++) s += __expf(v[i] - m);
        float nv = m + __logf(s) + lg[t * 25 + j];
        if (j < 25 && t < len) a = nv;
    }

    float m = a;
#pragma unroll
    for (int o = 16; o > 0; o >>= 1) m = fmaxf(m, __shfl_xor_sync(0xffffffffu, m, o));
    float e = (j < 25) ? __expf(a - m) : 0.f;
#pragma unroll
    for (int o = 16; o > 0; o >>= 1) e += __shfl_xor_sync(0xffffffffu, e, o);
    float logz = m + __logf(e);

    const int* tg = tags + (size_t)b * 256;
    float us = 0.f, bs = 0.f;
    for (int t = j; t < 256; t += 32) {
        if (t < len) {
            us += lg[t * 25 + tg[t]];
            if (t >= 1) bs += tr[tg[t - 1] * 25 + tg[t]];
        }
    }
#pragma unroll
    for (int o = 16; o > 0; o >>= 1) {
        us += __shfl_xor_sync(0xffffffffu, us, o);
        bs += __shfl_xor_sync(0xffffffffu, bs, o);
    }
    if (j == 0) g_nll[b] = -(us + bs - logz);
}

// ================= K5: loss = mean(nll) =================
__global__ __launch_bounds__(32) void loss_kernel(float* __restrict__ out)
{
    float v = g_nll[threadIdx.x];
#pragma unroll
    for (int o = 16; o > 0; o >>= 1) v += __shfl_xor_sync(0xffffffffu, v, o);
    if (threadIdx.x == 0) out[0] = v * (1.f / 32.f);
}

// ================= launcher =================
extern "C" void kernel_launch(void* const* d_in, const int* in_sizes, int n_in,
                              void* d_out, int out_size)
{
    const float* x     = (const float*)d_in[0];
    const int*   tags  = (const int*)d_in[1];
    const int*   lens  = (const int*)d_in[2];
    const float* kf    = (const float*)d_in[3];
    const float* rf    = (const float*)d_in[4];
    const float* bf    = (const float*)d_in[5];
    const float* kb    = (const float*)d_in[6];
    const float* rb    = (const float*)d_in[7];
    const float* bb    = (const float*)d_in[8];
    const float* dw    = (const float*)d_in[9];
    const float* db    = (const float*)d_in[10];
    const float* trans = (const float*)d_in[11];
    float* out = (float*)d_out;

    (void)in_sizes; (void)n_in; (void)out_size;

    // K0: transpose input weights
    dim3 gt(64, 24, 2);
    transpose_w<<<gt, 256>>>(kf, kb);

    // K1: tf32 mma.sync input projections
    dim3 g1(32, 64);
    xz_gemm_mma<<<g1, 256>>>(x, bf, bb);

    // K2: persistent recurrence (256 threads, 4-way K split)
    const size_t smem = (16384 + 16384 + 3 * 64 * 17) * sizeof(float);
    cudaFuncSetAttribute(lstm_kernel, cudaFuncAttributeMaxDynamicSharedMemorySize, (int)smem);
    lstm_kernel<<<128, 256, smem>>>(rf, rb);

    // K3: dense + SELU
    dense_kernel<<<1024, 256>>>(dw, db, out + 1);

    // K4: CRF per batch
    crf_kernel<<<32, 32>>>(out + 1, tags, lens, trans);

    // K5: mean loss
    loss_kernel<<<1, 32>>>(out);
}

// round 7
// speedup vs baseline: 2.1193x; 1.4384x over previous
#include <cuda_runtime.h>
#include <cstdint>
#include <cstddef>

// Problem dims: B=32, T=256, D=768, H=512, 4H=2048, N=25
// Output: d_out[0]=loss, d_out[1..]=logits[32,256,25]

// ---------------- scratch ----------------
__device__ __align__(16) float g_xz[2ull * 8192ull * 2048ull];   // [dir][t*32+b][2048]
__device__ __align__(16) float g_wT[2ull * 2048ull * 768ull];    // transposed input weights
__device__ __align__(16) float g_hs[8192ull * 1024ull];          // [b*256+t][fwd 512 | bwd 512]
__device__ __align__(16) float g_h[2 * 2 * 32 * 512];            // [dir][buf][b][u] (tf32-rounded)
__device__ float g_nll[32];
__device__ volatile int g_flags[128 * 32];                        // one 128B line per CTA
__device__ volatile int g_gen2;

#define SPIN_CAP (1 << 19)

// ---------------- fast grid barrier (parallel arrivals, bounded spins) ----------------
__device__ __forceinline__ void fast_barrier(int bx, int tid, int target) {
    __threadfence();
    __syncthreads();
    if (bx == 0) {
        if (tid > 0 && tid < 128) {
            int spins = 0;
            while (g_flags[tid * 32] < target) { if (++spins > SPIN_CAP) break; }
        }
        __syncthreads();
        if (tid == 0) { g_flags[0] = target; __threadfence(); g_gen2 = target; }
    } else {
        if (tid == 0) g_flags[bx * 32] = target;
    }
    if (tid == 0) {
        int spins = 0;
        while (g_gen2 < target) { if (++spins > SPIN_CAP) break; }
    }
    __syncthreads();
    __threadfence();
}

__device__ __forceinline__ float to_tf32(float x) {
    uint32_t r;
    asm("cvt.rna.tf32.f32 %0, %1;" : "=r"(r) : "f"(x));
    return __uint_as_float(r);
}

__device__ __forceinline__ void mma_tf32(float c[4], const uint32_t a[4], const uint32_t b[2]) {
    asm volatile(
        "mma.sync.aligned.m16n8k8.row.col.f32.tf32.tf32.f32 "
        "{%0,%1,%2,%3}, {%4,%5,%6,%7}, {%8,%9}, {%0,%1,%2,%3};"
        : "+f"(c[0]), "+f"(c[1]), "+f"(c[2]), "+f"(c[3])
        : "r"(a[0]), "r"(a[1]), "r"(a[2]), "r"(a[3]),
          "r"(b[0]), "r"(b[1]));
}

// ================= K0: transpose input weights -> g_wT[dir][n][k] =================
__global__ __launch_bounds__(256) void transpose_w(
    const float* __restrict__ kf, const float* __restrict__ kb)
{
    __shared__ float t[32][33];
    const int dir = blockIdx.z;
    const float* __restrict__ w = dir ? kb : kf;
    const int kb0 = blockIdx.y * 32;
    const int nb0 = blockIdx.x * 32;
    const int tx = threadIdx.x & 31, ty = threadIdx.x >> 5;
#pragma unroll
    for (int r = 0; r < 32; r += 8)
        t[ty + r][tx] = w[(size_t)(kb0 + ty + r) * 2048 + nb0 + tx];
    __syncthreads();
#pragma unroll
    for (int r = 0; r < 32; r += 8)
        g_wT[((size_t)dir * 2048 + nb0 + ty + r) * 768 + kb0 + tx] = t[tx][ty + r];
}

// ================= K1: xz = x @ K + b via mma.sync tf32 =================
__global__ __launch_bounds__(256, 2) void xz_gemm_mma(
    const float* __restrict__ x,
    const float* __restrict__ bf, const float* __restrict__ bb)
{
    __shared__ float As[2][128][20];
    __shared__ float Bs[2][16][136];

    const int m0 = blockIdx.y * 128;
    const int nb = blockIdx.x;            // 0..31
    const int dir = nb >> 4;
    const int n0 = (nb & 15) * 128;
    const float* __restrict__ wT = g_wT + (size_t)dir * 2048ull * 768ull;
    const float* __restrict__ bias = dir ? bb : bf;

    const int tid = threadIdx.x;
    const int warp = tid >> 5, lane = tid & 31;
    const int warpM = warp >> 1, warpN = warp & 1;
    const int mbase = warpM * 32, nbase = warpN * 64;
    const int gid = lane >> 2, tig = lane & 3;

    const int la_m = tid >> 1;
    const int la_k = (tid & 1) * 8;

    float c[2][8][4];
#pragma unroll
    for (int mi = 0; mi < 2; mi++)
#pragma unroll
        for (int ni = 0; ni < 8; ni++)
#pragma unroll
            for (int q = 0; q < 4; q++) c[mi][ni][q] = 0.f;

    {
        float4 a0 = *(const float4*)&x[(size_t)(m0 + la_m) * 768 + la_k];
        float4 a1 = *(const float4*)&x[(size_t)(m0 + la_m) * 768 + la_k + 4];
        As[0][la_m][la_k + 0] = to_tf32(a0.x); As[0][la_m][la_k + 1] = to_tf32(a0.y);
        As[0][la_m][la_k + 2] = to_tf32(a0.z); As[0][la_m][la_k + 3] = to_tf32(a0.w);
        As[0][la_m][la_k + 4] = to_tf32(a1.x); As[0][la_m][la_k + 5] = to_tf32(a1.y);
        As[0][la_m][la_k + 6] = to_tf32(a1.z); As[0][la_m][la_k + 7] = to_tf32(a1.w);
        float4 b0 = *(const float4*)&wT[(size_t)(n0 + la_m) * 768 + la_k];
        float4 b1 = *(const float4*)&wT[(size_t)(n0 + la_m) * 768 + la_k + 4];
        Bs[0][la_k + 0][la_m] = to_tf32(b0.x); Bs[0][la_k + 1][la_m] = to_tf32(b0.y);
        Bs[0][la_k + 2][la_m] = to_tf32(b0.z); Bs[0][la_k + 3][la_m] = to_tf32(b0.w);
        Bs[0][la_k + 4][la_m] = to_tf32(b1.x); Bs[0][la_k + 5][la_m] = to_tf32(b1.y);
        Bs[0][la_k + 6][la_m] = to_tf32(b1.z); Bs[0][la_k + 7][la_m] = to_tf32(b1.w);
    }
    __syncthreads();

    int buf = 0;
    for (int kt = 0; kt < 48; kt++) {
        float4 pa0, pa1, pb0, pb1;
        if (kt < 47) {
            const int k0 = (kt + 1) * 16;
            pa0 = *(const float4*)&x[(size_t)(m0 + la_m) * 768 + k0 + la_k];
            pa1 = *(const float4*)&x[(size_t)(m0 + la_m) * 768 + k0 + la_k + 4];
            pb0 = *(const float4*)&wT[(size_t)(n0 + la_m) * 768 + k0 + la_k];
            pb1 = *(const float4*)&wT[(size_t)(n0 + la_m) * 768 + k0 + la_k + 4];
        }

#pragma unroll
        for (int ks = 0; ks < 2; ks++) {
            const int kk = ks * 8;
            uint32_t af[2][4];
#pragma unroll
            for (int mi = 0; mi < 2; mi++) {
                const int r = mbase + mi * 16 + gid;
                af[mi][0] = __float_as_uint(As[buf][r][kk + tig]);
                af[mi][1] = __float_as_uint(As[buf][r + 8][kk + tig]);
                af[mi][2] = __float_as_uint(As[buf][r][kk + tig + 4]);
                af[mi][3] = __float_as_uint(As[buf][r + 8][kk + tig + 4]);
            }
            uint32_t bfr[8][2];
#pragma unroll
            for (int ni = 0; ni < 8; ni++) {
                const int col = nbase + ni * 8 + gid;
                bfr[ni][0] = __float_as_uint(Bs[buf][kk + tig][col]);
                bfr[ni][1] = __float_as_uint(Bs[buf][kk + tig + 4][col]);
            }
#pragma unroll
            for (int mi = 0; mi < 2; mi++)
#pragma unroll
                for (int ni = 0; ni < 8; ni++)
                    mma_tf32(c[mi][ni], af[mi], bfr[ni]);
        }

        if (kt < 47) {
            const int nbuf = buf ^ 1;
            As[nbuf][la_m][la_k + 0] = to_tf32(pa0.x); As[nbuf][la_m][la_k + 1] = to_tf32(pa0.y);
            As[nbuf][la_m][la_k + 2] = to_tf32(pa0.z); As[nbuf][la_m][la_k + 3] = to_tf32(pa0.w);
            As[nbuf][la_m][la_k + 4] = to_tf32(pa1.x); As[nbuf][la_m][la_k + 5] = to_tf32(pa1.y);
            As[nbuf][la_m][la_k + 6] = to_tf32(pa1.z); As[nbuf][la_m][la_k + 7] = to_tf32(pa1.w);
            Bs[nbuf][la_k + 0][la_m] = to_tf32(pb0.x); Bs[nbuf][la_k + 1][la_m] = to_tf32(pb0.y);
            Bs[nbuf][la_k + 2][la_m] = to_tf32(pb0.z); Bs[nbuf][la_k + 3][la_m] = to_tf32(pb0.w);
            Bs[nbuf][la_k + 4][la_m] = to_tf32(pb1.x); Bs[nbuf][la_k + 5][la_m] = to_tf32(pb1.y);
            Bs[nbuf][la_k + 6][la_m] = to_tf32(pb1.z); Bs[nbuf][la_k + 7][la_m] = to_tf32(pb1.w);
        }
        __syncthreads();
        buf ^= 1;
    }

    float* outp = g_xz + (size_t)dir * (8192ull * 2048ull);
#pragma unroll
    for (int mi = 0; mi < 2; mi++) {
        const int r0 = m0 + mbase + mi * 16 + gid;
        const int r1 = r0 + 8;
        const size_t o0 = (size_t)((r0 & 255) * 32 + (r0 >> 8)) * 2048;
        const size_t o1 = (size_t)((r1 & 255) * 32 + (r1 >> 8)) * 2048;
#pragma unroll
        for (int ni = 0; ni < 8; ni++) {
            const int cc = n0 + nbase + ni * 8 + tig * 2;
            float2 b2 = *(const float2*)&bias[cc];
            float2 v0 = { c[mi][ni][0] + b2.x, c[mi][ni][1] + b2.y };
            float2 v1 = { c[mi][ni][2] + b2.x, c[mi][ni][3] + b2.y };
            *(float2*)&outp[o0 + cc] = v0;
            *(float2*)&outp[o1 + cc] = v1;
        }
    }
}

// ================= K2: persistent BiLSTM recurrence via mma.sync tf32 =================
// 128 CTAs (64/dir) x 256 threads (8 warps). CTA owns 8 hidden units (32 gate cols).
// Per step: C[32 batch, 32 cols] = h[32,512] @ W[512,32]; warp w owns K slice [64w,64w+64)
// with its W slice resident in registers as mma B-fragments.
__global__ __launch_bounds__(256, 1) void lstm_mma_kernel(
    const float* __restrict__ rf, const float* __restrict__ rb)
{
    const int bx  = blockIdx.x;       // 0..127
    const int dir = bx >> 6;
    const int u0  = (bx & 63) * 8;
    const int tid = threadIdx.x;
    const int warp = tid >> 5, lane = tid & 31;
    const int gid = lane >> 2, tig = lane & 3;
    const int eb = tid >> 3;          // epilogue: batch 0..31
    const int eu = tid & 7;           // epilogue: unit 0..7

    extern __shared__ float smem[];
    float* h_s = smem;                 // [32][516] tf32 bits (pad: conflict-free A LDS)
    float* red = smem + 32 * 516;      // [8 warps][32][36]

    // ---- resident W fragments: warp w -> k in [64w, 64w+64) ----
    const float* __restrict__ rec = dir ? rb : rf;
    uint32_t bw[4][8][2];
#pragma unroll
    for (int ni = 0; ni < 4; ni++) {
        const int colc = ni * 8 + gid;                       // 0..31
        const int colg = (colc & 3) * 512 + u0 + (colc >> 2);
#pragma unroll
        for (int kc = 0; kc < 8; kc++) {
            const int k0 = warp * 64 + kc * 8;
            bw[ni][kc][0] = __float_as_uint(to_tf32(rec[(size_t)(k0 + tig) * 2048 + colg]));
            bw[ni][kc][1] = __float_as_uint(to_tf32(rec[(size_t)(k0 + tig + 4) * 2048 + colg]));
        }
    }

    const float* __restrict__ xz = g_xz + (size_t)dir * (8192ull * 2048ull);
    float* hbase = g_h + dir * 32768;
    float c_st = 0.f;
    const int base = g_flags[bx * 32];
    __syncthreads();

    for (int t = 0; t < 256; t++) {
        const int txi = dir ? (255 - t) : t;

        // xz for this thread's (batch, unit): 4 gates
        float z[4];
        {
            const float* slab = xz + ((size_t)txi * 32 + eb) * 2048 + u0 + eu;
#pragma unroll
            for (int g = 0; g < 4; g++) z[g] = slab[g * 512];
        }

        if (t > 0) {
            // fill h_s (tf32 bits, padded stride 516) from global prev buffer
            const float4* h4 = (const float4*)(hbase + ((t + 1) & 1) * 16384);
#pragma unroll
            for (int j = 0; j < 16; j++) {
                int i = tid + j * 256;
                float4 v = h4[i];
                int b = i >> 7, k4 = i & 127;
                *(float4*)&h_s[b * 516 + k4 * 4] = v;
            }
            __syncthreads();

            float c[2][4][4];
#pragma unroll
            for (int mi = 0; mi < 2; mi++)
#pragma unroll
                for (int ni = 0; ni < 4; ni++)
#pragma unroll
                    for (int q = 0; q < 4; q++) c[mi][ni][q] = 0.f;

#pragma unroll
            for (int kc = 0; kc < 8; kc++) {
                const int k0 = warp * 64 + kc * 8;
                uint32_t af[2][4];
#pragma unroll
                for (int mi = 0; mi < 2; mi++) {
                    const int r = mi * 16 + gid;
                    af[mi][0] = __float_as_uint(h_s[r * 516 + k0 + tig]);
                    af[mi][1] = __float_as_uint(h_s[(r + 8) * 516 + k0 + tig]);
                    af[mi][2] = __float_as_uint(h_s[r * 516 + k0 + tig + 4]);
                    af[mi][3] = __float_as_uint(h_s[(r + 8) * 516 + k0 + tig + 4]);
                }
#pragma unroll
                for (int mi = 0; mi < 2; mi++)
#pragma unroll
                    for (int ni = 0; ni < 4; ni++)
                        mma_tf32(c[mi][ni], af[mi], bw[ni][kc]);
            }

            // partial C -> red[warp][row][col]
            float* rw = red + warp * 1152;
#pragma unroll
            for (int mi = 0; mi < 2; mi++) {
                const int row = mi * 16 + gid;
#pragma unroll
                for (int ni = 0; ni < 4; ni++) {
                    const int cc = ni * 8 + tig * 2;
                    *(float2*)&rw[row * 36 + cc] = make_float2(c[mi][ni][0], c[mi][ni][1]);
                    *(float2*)&rw[(row + 8) * 36 + cc] = make_float2(c[mi][ni][2], c[mi][ni][3]);
                }
            }
            __syncthreads();

            // reduce across 8 warps: this thread owns (eb, eu) -> cols eu*4..eu*4+3
#pragma unroll
            for (int w = 0; w < 8; w++) {
                float4 v = *(const float4*)&red[w * 1152 + eb * 36 + eu * 4];
                z[0] += v.x; z[1] += v.y; z[2] += v.z; z[3] += v.w;
            }
        }

        // activation (one (batch, unit) cell per thread)
        float ig = 1.f / (1.f + __expf(-z[0]));
        float fg = 1.f / (1.f + __expf(-z[1]));
        float gg = tanhf(z[2]);
        float og = 1.f / (1.f + __expf(-z[3]));
        c_st = fmaf(fg, c_st, ig * gg);
        float h = og * tanhf(c_st);

        hbase[(t & 1) * 16384 + eb * 512 + u0 + eu] = to_tf32(h);
        g_hs[((size_t)eb * 256 + txi) * 1024 + dir * 512 + u0 + eu] = h;

        fast_barrier(bx, tid, base + t + 1);
    }
}

// ================= K3: dense + SELU =================
__global__ __launch_bounds__(256) void dense_kernel(
    const float* __restrict__ W, const float* __restrict__ bias, float* __restrict__ logits)
{
    int warp = (blockIdx.x * blockDim.x + threadIdx.x) >> 5;
    int lane = threadIdx.x & 31;
    if (warp >= 8192) return;
    const float4* h4 = (const float4*)(g_hs + (size_t)warp * 1024);
    float acc = (lane < 25) ? bias[lane] : 0.f;
#pragma unroll 4
    for (int k4 = 0; k4 < 256; k4++) {
        float4 h = h4[k4];
        int k = k4 * 4;
        if (lane < 25) {
            acc = fmaf(h.x, W[(k + 0) * 25 + lane], acc);
            acc = fmaf(h.y, W[(k + 1) * 25 + lane], acc);
            acc = fmaf(h.z, W[(k + 2) * 25 + lane], acc);
            acc = fmaf(h.w, W[(k + 3) * 25 + lane], acc);
        }
    }
    if (lane < 25) {
        float y = acc;
        y = 1.0507009873554805f * (y > 0.f ? y : 1.6732632423543772f * (__expf(y) - 1.f));
        logits[(size_t)warp * 25 + lane] = y;
    }
}

// ================= K4: CRF NLL per batch (register alpha + shfl) =================
__global__ __launch_bounds__(32) void crf_kernel(
    const float* __restrict__ logits, const int* __restrict__ tags,
    const int* __restrict__ lens, const float* __restrict__ trans)
{
    const int b = blockIdx.x;
    const int j = threadIdx.x;
    __shared__ float tr[625];
    for (int i = j; i < 625; i += 32) tr[i] = trans[i];
    int len = lens[b];
    if (len < 1) len = 1;
    if (len > 256) len = 256;
    const float* lg = logits + (size_t)b * 256 * 25;
    __syncthreads();

    float a = (j < 25) ? lg[j] : -1e30f;
    for (int t = 1; t < 256; t++) {
        float m = -1e30f;
        float v[25];
#pragma unroll
        for (int i = 0; i < 25; i++) {
            v[i] = __shfl_sync(0xffffffffu, a, i) + tr[i * 25 + j];
            m = fmaxf(m, v[i]);
        }
        float s = 0.f;
#pragma unroll
        for (int i = 0; i < 25; i++) s += __expf(v[i] - m);
        float nv = m + __logf(s) + lg[t * 25 + j];
        if (j < 25 && t < len) a = nv;
    }

    float m = a;
#pragma unroll
    for (int o = 16; o > 0; o >>= 1) m = fmaxf(m, __shfl_xor_sync(0xffffffffu, m, o));
    float e = (j < 25) ? __expf(a - m) : 0.f;
#pragma unroll
    for (int o = 16; o > 0; o >>= 1) e += __shfl_xor_sync(0xffffffffu, e, o);
    float logz = m + __logf(e);

    const int* tg = tags + (size_t)b * 256;
    float us = 0.f, bs = 0.f;
    for (int t = j; t < 256; t += 32) {
        if (t < len) {
            us += lg[t * 25 + tg[t]];
            if (t >= 1) bs += tr[tg[t - 1] * 25 + tg[t]];
        }
    }
#pragma unroll
    for (int o = 16; o > 0; o >>= 1) {
        us += __shfl_xor_sync(0xffffffffu, us, o);
        bs += __shfl_xor_sync(0xffffffffu, bs, o);
    }
    if (j == 0) g_nll[b] = -(us + bs - logz);
}

// ================= K5: loss = mean(nll) =================
__global__ __launch_bounds__(32) void loss_kernel(float* __restrict__ out)
{
    float v = g_nll[threadIdx.x];
#pragma unroll
    for (int o = 16; o > 0; o >>= 1) v += __shfl_xor_sync(0xffffffffu, v, o);
    if (threadIdx.x == 0) out[0] = v * (1.f / 32.f);
}

// ================= launcher =================
extern "C" void kernel_launch(void* const* d_in, const int* in_sizes, int n_in,
                              void* d_out, int out_size)
{
    const float* x     = (const float*)d_in[0];
    const int*   tags  = (const int*)d_in[1];
    const int*   lens  = (const int*)d_in[2];
    const float* kf    = (const float*)d_in[3];
    const float* rf    = (const float*)d_in[4];
    const float* bf    = (const float*)d_in[5];
    const float* kb    = (const float*)d_in[6];
    const float* rb    = (const float*)d_in[7];
    const float* bb    = (const float*)d_in[8];
    const float* dw    = (const float*)d_in[9];
    const float* db    = (const float*)d_in[10];
    const float* trans = (const float*)d_in[11];
    float* out = (float*)d_out;

    (void)in_sizes; (void)n_in; (void)out_size;

    // K0: transpose input weights
    dim3 gt(64, 24, 2);
    transpose_w<<<gt, 256>>>(kf, kb);

    // K1: tf32 mma.sync input projections
    dim3 g1(32, 64);
    xz_gemm_mma<<<g1, 256>>>(x, bf, bb);

    // K2: persistent recurrence, tensor-core
    const size_t smem = (32 * 516 + 8 * 1152) * sizeof(float);
    cudaFuncSetAttribute(lstm_mma_kernel, cudaFuncAttributeMaxDynamicSharedMemorySize, (int)smem);
    lstm_mma_kernel<<<128, 256, smem>>>(rf, rb);

    // K3: dense + SELU
    dense_kernel<<<1024, 256>>>(dw, db, out + 1);

    // K4: CRF per batch
    crf_kernel<<<32, 32>>>(out + 1, tags, lens, trans);

    // K5: mean loss
    loss_kernel<<<1, 32>>>(out);
}

// round 9
// speedup vs baseline: 2.3755x; 1.1209x over previous
#include <cuda_runtime.h>
#include <cuda_bf16.h>
#include <cstdint>
#include <cstddef>

// Problem dims: B=32, T=256, D=768, H=512, 4H=2048, N=25
// Output: d_out[0]=loss, d_out[1..]=logits[32,256,25]

// ---------------- scratch ----------------
__device__ __align__(16) float g_xz[2ull * 8192ull * 2048ull];   // [dir][t*32+b][2048]
__device__ __align__(16) float g_wT[2ull * 2048ull * 768ull];    // transposed input weights
__device__ __align__(16) float g_hs[8192ull * 1024ull];          // [b*256+t][fwd 512 | bwd 512]
__device__ __align__(16) unsigned short g_h16[2 * 2 * 32 * 512]; // [dir][buf][b][u] bf16
__device__ float g_nll[32];
__device__ volatile int g_flags[128 * 32];                        // one 128B line per CTA
__device__ volatile int g_gen2;

#define SPIN_CAP (1 << 19)

// ---------------- all-to-all grid barrier (bounded spins) ----------------
__device__ __forceinline__ void fast_barrier(int bx, int tid, int target) {
    __threadfence();
    __syncthreads();
    if (tid == 0) g_flags[bx * 32] = target;
    if (tid < 128) {
        int spins = 0;
        while (g_flags[tid * 32] < target) { if (++spins > SPIN_CAP) break; }
    }
    __syncthreads();
    __threadfence();
}

__device__ __forceinline__ float to_tf32(float x) {
    uint32_t r;
    asm("cvt.rna.tf32.f32 %0, %1;" : "=r"(r) : "f"(x));
    return __uint_as_float(r);
}

__device__ __forceinline__ void mma_tf32(float c[4], const uint32_t a[4], const uint32_t b[2]) {
    asm volatile(
        "mma.sync.aligned.m16n8k8.row.col.f32.tf32.tf32.f32 "
        "{%0,%1,%2,%3}, {%4,%5,%6,%7}, {%8,%9}, {%0,%1,%2,%3};"
        : "+f"(c[0]), "+f"(c[1]), "+f"(c[2]), "+f"(c[3])
        : "r"(a[0]), "r"(a[1]), "r"(a[2]), "r"(a[3]),
          "r"(b[0]), "r"(b[1]));
}

__device__ __forceinline__ void mma_bf16(float c[4], const uint32_t a[4], const uint32_t b[2]) {
    asm volatile(
        "mma.sync.aligned.m16n8k16.row.col.f32.bf16.bf16.f32 "
        "{%0,%1,%2,%3}, {%4,%5,%6,%7}, {%8,%9}, {%0,%1,%2,%3};"
        : "+f"(c[0]), "+f"(c[1]), "+f"(c[2]), "+f"(c[3])
        : "r"(a[0]), "r"(a[1]), "r"(a[2]), "r"(a[3]),
          "r"(b[0]), "r"(b[1]));
}

__device__ __forceinline__ unsigned short f2bf(float x) {
    return __bfloat16_as_ushort(__float2bfloat16_rn(x));
}
__device__ __forceinline__ float bf2f(unsigned short u) {
    return __bfloat162float(__ushort_as_bfloat16(u));
}

// ================= K0: transpose input weights -> g_wT[dir][n][k] =================
__global__ __launch_bounds__(256) void transpose_w(
    const float* __restrict__ kf, const float* __restrict__ kb)
{
    __shared__ float t[32][33];
    const int dir = blockIdx.z;
    const float* __restrict__ w = dir ? kb : kf;
    const int kb0 = blockIdx.y * 32;
    const int nb0 = blockIdx.x * 32;
    const int tx = threadIdx.x & 31, ty = threadIdx.x >> 5;
#pragma unroll
    for (int r = 0; r < 32; r += 8)
        t[ty + r][tx] = w[(size_t)(kb0 + ty + r) * 2048 + nb0 + tx];
    __syncthreads();
#pragma unroll
    for (int r = 0; r < 32; r += 8)
        g_wT[((size_t)dir * 2048 + nb0 + ty + r) * 768 + kb0 + tx] = t[tx][ty + r];
}

// ================= K1: xz = x @ K + b via mma.sync tf32 =================
__global__ __launch_bounds__(256, 2) void xz_gemm_mma(
    const float* __restrict__ x,
    const float* __restrict__ bf, const float* __restrict__ bb)
{
    __shared__ float As[2][128][20];
    __shared__ float Bs[2][16][136];

    const int m0 = blockIdx.y * 128;
    const int nb = blockIdx.x;            // 0..31
    const int dir = nb >> 4;
    const int n0 = (nb & 15) * 128;
    const float* __restrict__ wT = g_wT + (size_t)dir * 2048ull * 768ull;
    const float* __restrict__ bias = dir ? bb : bf;

    const int tid = threadIdx.x;
    const int warp = tid >> 5, lane = tid & 31;
    const int warpM = warp >> 1, warpN = warp & 1;
    const int mbase = warpM * 32, nbase = warpN * 64;
    const int gid = lane >> 2, tig = lane & 3;

    const int la_m = tid >> 1;
    const int la_k = (tid & 1) * 8;

    float c[2][8][4];
#pragma unroll
    for (int mi = 0; mi < 2; mi++)
#pragma unroll
        for (int ni = 0; ni < 8; ni++)
#pragma unroll
            for (int q = 0; q < 4; q++) c[mi][ni][q] = 0.f;

    {
        float4 a0 = *(const float4*)&x[(size_t)(m0 + la_m) * 768 + la_k];
        float4 a1 = *(const float4*)&x[(size_t)(m0 + la_m) * 768 + la_k + 4];
        As[0][la_m][la_k + 0] = to_tf32(a0.x); As[0][la_m][la_k + 1] = to_tf32(a0.y);
        As[0][la_m][la_k + 2] = to_tf32(a0.z); As[0][la_m][la_k + 3] = to_tf32(a0.w);
        As[0][la_m][la_k + 4] = to_tf32(a1.x); As[0][la_m][la_k + 5] = to_tf32(a1.y);
        As[0][la_m][la_k + 6] = to_tf32(a1.z); As[0][la_m][la_k + 7] = to_tf32(a1.w);
        float4 b0 = *(const float4*)&wT[(size_t)(n0 + la_m) * 768 + la_k];
        float4 b1 = *(const float4*)&wT[(size_t)(n0 + la_m) * 768 + la_k + 4];
        Bs[0][la_k + 0][la_m] = to_tf32(b0.x); Bs[0][la_k + 1][la_m] = to_tf32(b0.y);
        Bs[0][la_k + 2][la_m] = to_tf32(b0.z); Bs[0][la_k + 3][la_m] = to_tf32(b0.w);
        Bs[0][la_k + 4][la_m] = to_tf32(b1.x); Bs[0][la_k + 5][la_m] = to_tf32(b1.y);
        Bs[0][la_k + 6][la_m] = to_tf32(b1.z); Bs[0][la_k + 7][la_m] = to_tf32(b1.w);
    }
    __syncthreads();

    int buf = 0;
    for (int kt = 0; kt < 48; kt++) {
        float4 pa0, pa1, pb0, pb1;
        if (kt < 47) {
            const int k0 = (kt + 1) * 16;
            pa0 = *(const float4*)&x[(size_t)(m0 + la_m) * 768 + k0 + la_k];
            pa1 = *(const float4*)&x[(size_t)(m0 + la_m) * 768 + k0 + la_k + 4];
            pb0 = *(const float4*)&wT[(size_t)(n0 + la_m) * 768 + k0 + la_k];
            pb1 = *(const float4*)&wT[(size_t)(n0 + la_m) * 768 + k0 + la_k + 4];
        }

#pragma unroll
        for (int ks = 0; ks < 2; ks++) {
            const int kk = ks * 8;
            uint32_t af[2][4];
#pragma unroll
            for (int mi = 0; mi < 2; mi++) {
                const int r = mbase + mi * 16 + gid;
                af[mi][0] = __float_as_uint(As[buf][r][kk + tig]);
                af[mi][1] = __float_as_uint(As[buf][r + 8][kk + tig]);
                af[mi][2] = __float_as_uint(As[buf][r][kk + tig + 4]);
                af[mi][3] = __float_as_uint(As[buf][r + 8][kk + tig + 4]);
            }
            uint32_t bfr[8][2];
#pragma unroll
            for (int ni = 0; ni < 8; ni++) {
                const int col = nbase + ni * 8 + gid;
                bfr[ni][0] = __float_as_uint(Bs[buf][kk + tig][col]);
                bfr[ni][1] = __float_as_uint(Bs[buf][kk + tig + 4][col]);
            }
#pragma unroll
            for (int mi = 0; mi < 2; mi++)
#pragma unroll
                for (int ni = 0; ni < 8; ni++)
                    mma_tf32(c[mi][ni], af[mi], bfr[ni]);
        }

        if (kt < 47) {
            const int nbuf = buf ^ 1;
            As[nbuf][la_m][la_k + 0] = to_tf32(pa0.x); As[nbuf][la_m][la_k + 1] = to_tf32(pa0.y);
            As[nbuf][la_m][la_k + 2] = to_tf32(pa0.z); As[nbuf][la_m][la_k + 3] = to_tf32(pa0.w);
            As[nbuf][la_m][la_k + 4] = to_tf32(pa1.x); As[nbuf][la_m][la_k + 5] = to_tf32(pa1.y);
            As[nbuf][la_m][la_k + 6] = to_tf32(pa1.z); As[nbuf][la_m][la_k + 7] = to_tf32(pa1.w);
            Bs[nbuf][la_k + 0][la_m] = to_tf32(pb0.x); Bs[nbuf][la_k + 1][la_m] = to_tf32(pb0.y);
            Bs[nbuf][la_k + 2][la_m] = to_tf32(pb0.z); Bs[nbuf][la_k + 3][la_m] = to_tf32(pb0.w);
            Bs[nbuf][la_k + 4][la_m] = to_tf32(pb1.x); Bs[nbuf][la_k + 5][la_m] = to_tf32(pb1.y);
            Bs[nbuf][la_k + 6][la_m] = to_tf32(pb1.z); Bs[nbuf][la_k + 7][la_m] = to_tf32(pb1.w);
        }
        __syncthreads();
        buf ^= 1;
    }

    float* outp = g_xz + (size_t)dir * (8192ull * 2048ull);
#pragma unroll
    for (int mi = 0; mi < 2; mi++) {
        const int r0 = m0 + mbase + mi * 16 + gid;
        const int r1 = r0 + 8;
        const size_t o0 = (size_t)((r0 & 255) * 32 + (r0 >> 8)) * 2048;
        const size_t o1 = (size_t)((r1 & 255) * 32 + (r1 >> 8)) * 2048;
#pragma unroll
        for (int ni = 0; ni < 8; ni++) {
            const int cc = n0 + nbase + ni * 8 + tig * 2;
            float2 b2 = *(const float2*)&bias[cc];
            float2 v0 = { c[mi][ni][0] + b2.x, c[mi][ni][1] + b2.y };
            float2 v1 = { c[mi][ni][2] + b2.x, c[mi][ni][3] + b2.y };
            *(float2*)&outp[o0 + cc] = v0;
            *(float2*)&outp[o1 + cc] = v1;
        }
    }
}

// ================= K2: persistent BiLSTM recurrence, bf16 h + hi/lo W =================
// 128 CTAs (64/dir) x 256 threads (8 warps). CTA owns 8 hidden units (32 gate cols).
// Per step: C[32,32] = h[32,512](bf16) @ (W_hi + W_lo)[512,32](bf16), fp32 accum.
// Warp w owns K slice [64w, 64w+64): 4 k16-chunks, W frags resident in registers.
__global__ __launch_bounds__(256, 1) void lstm_mma_kernel(
    const float* __restrict__ rf, const float* __restrict__ rb)
{
    const int bx  = blockIdx.x;       // 0..127
    const int dir = bx >> 6;
    const int u0  = (bx & 63) * 8;
    const int tid = threadIdx.x;
    const int warp = tid >> 5, lane = tid & 31;
    const int gid = lane >> 2, tig = lane & 3;
    const int eb = tid >> 3;          // epilogue: batch 0..31
    const int eu = tid & 7;           // epilogue: unit 0..7

    extern __shared__ float smem[];
    unsigned short* h_s = (unsigned short*)smem;   // [32][520] bf16 (pad: addr4 stride 260 ≡ 4 mod 32)
    float* red = smem + 8320;                      // [8 warps][32][36]

    // ---- resident W fragments (hi/lo bf16 split): warp w -> k in [64w, 64w+64) ----
    const float* __restrict__ rec = dir ? rb : rf;
    uint32_t bw_hi[4][4][2], bw_lo[4][4][2];
#pragma unroll
    for (int ni = 0; ni < 4; ni++) {
        const int colc = ni * 8 + gid;                       // 0..31
        const int colg = (colc & 3) * 512 + u0 + (colc >> 2);
#pragma unroll
        for (int kc = 0; kc < 4; kc++) {
            const int k0 = warp * 64 + kc * 16;
#pragma unroll
            for (int q = 0; q < 2; q++) {
                const int ka = k0 + 2 * tig + q * 8;
                float w0 = rec[(size_t)ka * 2048 + colg];
                float w1 = rec[(size_t)(ka + 1) * 2048 + colg];
                unsigned short h0 = f2bf(w0), h1 = f2bf(w1);
                unsigned short l0 = f2bf(w0 - bf2f(h0)), l1 = f2bf(w1 - bf2f(h1));
                bw_hi[ni][kc][q] = (uint32_t)h0 | ((uint32_t)h1 << 16);
                bw_lo[ni][kc][q] = (uint32_t)l0 | ((uint32_t)l1 << 16);
            }
        }
    }

    const float* __restrict__ xz = g_xz + (size_t)dir * (8192ull * 2048ull);
    unsigned short* hbase = g_h16 + dir * 32768;  // two 16384-half buffers
    float c_st = 0.f;
    const int base = g_flags[bx * 32];
    __syncthreads();

    for (int t = 0; t < 256; t++) {
        const int txi = dir ? (255 - t) : t;

        // xz for this thread's (batch, unit): 4 gates
        float z[4];
        {
            const float* slab = xz + ((size_t)txi * 32 + eb) * 2048 + u0 + eu;
#pragma unroll
            for (int g = 0; g < 4; g++) z[g] = slab[g * 512];
        }

        if (t > 0) {
            // fill h_s (bf16, padded row stride 520 halfs) from global prev buffer (L2)
            const uint4* h4 = (const uint4*)(hbase + ((t + 1) & 1) * 16384);
#pragma unroll
            for (int j = 0; j < 8; j++) {
                int i = tid + j * 256;         // 0..2047 uint4s
                uint4 v = __ldcg(&h4[i]);
                int b = i >> 6, kq = i & 63;
                *(uint4*)&h_s[b * 520 + kq * 8] = v;
            }
            __syncthreads();

            float c[2][4][4];
#pragma unroll
            for (int mi = 0; mi < 2; mi++)
#pragma unroll
                for (int ni = 0; ni < 4; ni++)
#pragma unroll
                    for (int q = 0; q < 4; q++) c[mi][ni][q] = 0.f;

            const uint32_t* hs4 = (const uint32_t*)h_s;   // stride 260 per row
#pragma unroll
            for (int kc = 0; kc < 4; kc++) {
                const int kh = warp * 32 + kc * 8 + tig;  // in 2-half units
                uint32_t af[2][4];
#pragma unroll
                for (int mi = 0; mi < 2; mi++) {
                    const int r = mi * 16 + gid;
                    af[mi][0] = hs4[r * 260 + kh];
                    af[mi][1] = hs4[(r + 8) * 260 + kh];
                    af[mi][2] = hs4[r * 260 + kh + 4];
                    af[mi][3] = hs4[(r + 8) * 260 + kh + 4];
                }
#pragma unroll
                for (int mi = 0; mi < 2; mi++)
#pragma unroll
                    for (int ni = 0; ni < 4; ni++) {
                        mma_bf16(c[mi][ni], af[mi], bw_hi[ni][kc]);
                        mma_bf16(c[mi][ni], af[mi], bw_lo[ni][kc]);
                    }
            }

            // partial C -> red[warp][row][col]
            float* rw = red + warp * 1152;
#pragma unroll
            for (int mi = 0; mi < 2; mi++) {
                const int row = mi * 16 + gid;
#pragma unroll
                for (int ni = 0; ni < 4; ni++) {
                    const int cc = ni * 8 + tig * 2;
                    *(float2*)&rw[row * 36 + cc] = make_float2(c[mi][ni][0], c[mi][ni][1]);
                    *(float2*)&rw[(row + 8) * 36 + cc] = make_float2(c[mi][ni][2], c[mi][ni][3]);
                }
            }
            __syncthreads();

            // reduce across 8 warps: this thread owns (eb, eu) -> cols eu*4..eu*4+3
#pragma unroll
            for (int w = 0; w < 8; w++) {
                float4 v = *(const float4*)&red[w * 1152 + eb * 36 + eu * 4];
                z[0] += v.x; z[1] += v.y; z[2] += v.z; z[3] += v.w;
            }
        }

        // activation (one (batch, unit) cell per thread)
        float ig = 1.f / (1.f + __expf(-z[0]));
        float fg = 1.f / (1.f + __expf(-z[1]));
        float gg = tanhf(z[2]);
        float og = 1.f / (1.f + __expf(-z[3]));
        c_st = fmaf(fg, c_st, ig * gg);
        float h = og * tanhf(c_st);

        hbase[(t & 1) * 16384 + eb * 512 + u0 + eu] = f2bf(h);
        g_hs[((size_t)eb * 256 + txi) * 1024 + dir * 512 + u0 + eu] = h;

        fast_barrier(bx, tid, base + t + 1);
    }
}

// ================= K3: dense + SELU =================
__global__ __launch_bounds__(256) void dense_kernel(
    const float* __restrict__ W, const float* __restrict__ bias, float* __restrict__ logits)
{
    int warp = (blockIdx.x * blockDim.x + threadIdx.x) >> 5;
    int lane = threadIdx.x & 31;
    if (warp >= 8192) return;
    const float4* h4 = (const float4*)(g_hs + (size_t)warp * 1024);
    float acc = (lane < 25) ? bias[lane] : 0.f;
#pragma unroll 4
    for (int k4 = 0; k4 < 256; k4++) {
        float4 h = h4[k4];
        int k = k4 * 4;
        if (lane < 25) {
            acc = fmaf(h.x, W[(k + 0) * 25 + lane], acc);
            acc = fmaf(h.y, W[(k + 1) * 25 + lane], acc);
            acc = fmaf(h.z, W[(k + 2) * 25 + lane], acc);
            acc = fmaf(h.w, W[(k + 3) * 25 + lane], acc);
        }
    }
    if (lane < 25) {
        float y = acc;
        y = 1.0507009873554805f * (y > 0.f ? y : 1.6732632423543772f * (__expf(y) - 1.f));
        logits[(size_t)warp * 25 + lane] = y;
    }
}

// ================= K4: CRF NLL per batch (register alpha + shfl) =================
__global__ __launch_bounds__(32) void crf_kernel(
    const float* __restrict__ logits, const int* __restrict__ tags,
    const int* __restrict__ lens, const float* __restrict__ trans)
{
    const int b = blockIdx.x;
    const int j = threadIdx.x;
    __shared__ float tr[625];
    for (int i = j; i < 625; i += 32) tr[i] = trans[i];
    int len = lens[b];
    if (len < 1) len = 1;
    if (len > 256) len = 256;
    const float* lg = logits + (size_t)b * 256 * 25;
    __syncthreads();

    float a = (j < 25) ? lg[j] : -1e30f;
    for (int t = 1; t < 256; t++) {
        float m = -1e30f;
        float v[25];
#pragma unroll
        for (int i = 0; i < 25; i++) {
            v[i] = __shfl_sync(0xffffffffu, a, i) + tr[i * 25 + j];
            m = fmaxf(m, v[i]);
        }
        float s = 0.f;
#pragma unroll
        for (int i = 0; i < 25; i++) s += __expf(v[i] - m);
        float nv = m + __logf(s) + lg[t * 25 + j];
        if (j < 25 && t < len) a = nv;
    }

    float m = a;
#pragma unroll
    for (int o = 16; o > 0; o >>= 1) m = fmaxf(m, __shfl_xor_sync(0xffffffffu, m, o));
    float e = (j < 25) ? __expf(a - m) : 0.f;
#pragma unroll
    for (int o = 16; o > 0; o >>= 1) e += __shfl_xor_sync(0xffffffffu, e, o);
    float logz = m + __logf(e);

    const int* tg = tags + (size_t)b * 256;
    float us = 0.f, bs = 0.f;
    for (int t = j; t < 256; t += 32) {
        if (t < len) {
            us += lg[t * 25 + tg[t]];
            if (t >= 1) bs += tr[tg[t - 1] * 25 + tg[t]];
        }
    }
#pragma unroll
    for (int o = 16; o > 0; o >>= 1) {
        us += __shfl_xor_sync(0xffffffffu, us, o);
        bs += __shfl_xor_sync(0xffffffffu, bs, o);
    }
    if (j == 0) g_nll[b] = -(us + bs - logz);
}

// ================= K5: loss = mean(nll) =================
__global__ __launch_bounds__(32) void loss_kernel(float* __restrict__ out)
{
    float v = g_nll[threadIdx.x];
#pragma unroll
    for (int o = 16; o > 0; o >>= 1) v += __shfl_xor_sync(0xffffffffu, v, o);
    if (threadIdx.x == 0) out[0] = v * (1.f / 32.f);
}

// ================= launcher =================
extern "C" void kernel_launch(void* const* d_in, const int* in_sizes, int n_in,
                              void* d_out, int out_size)
{
    const float* x     = (const float*)d_in[0];
    const int*   tags  = (const int*)d_in[1];
    const int*   lens  = (const int*)d_in[2];
    const float* kf    = (const float*)d_in[3];
    const float* rf    = (const float*)d_in[4];
    const float* bf    = (const float*)d_in[5];
    const float* kb    = (const float*)d_in[6];
    const float* rb    = (const float*)d_in[7];
    const float* bb    = (const float*)d_in[8];
    const float* dw    = (const float*)d_in[9];
    const float* db    = (const float*)d_in[10];
    const float* trans = (const float*)d_in[11];
    float* out = (float*)d_out;

    (void)in_sizes; (void)n_in; (void)out_size;

    // K0: transpose input weights
    dim3 gt(64, 24, 2);
    transpose_w<<<gt, 256>>>(kf, kb);

    // K1: tf32 mma.sync input projections
    dim3 g1(32, 64);
    xz_gemm_mma<<<g1, 256>>>(x, bf, bb);

    // K2: persistent recurrence, bf16 tensor-core
    // smem: h_s 32*520 halfs (= 8320 floats) + red 8*1152 floats
    const size_t smem = (8320 + 8 * 1152) * sizeof(float);
    cudaFuncSetAttribute(lstm_mma_kernel, cudaFuncAttributeMaxDynamicSharedMemorySize, (int)smem);
    lstm_mma_kernel<<<128, 256, smem>>>(rf, rb);

    // K3: dense + SELU
    dense_kernel<<<1024, 256>>>(dw, db, out + 1);

    // K4: CRF per batch
    crf_kernel<<<32, 32>>>(out + 1, tags, lens, trans);

    // K5: mean loss
    loss_kernel<<<1, 32>>>(out);
}